// round 12
// baseline (speedup 1.0000x reference)
#include <cuda_runtime.h>
#include <cuda_bf16.h>
#include <cuda_fp16.h>
#include <mma.h>
#include <math.h>
#include <stdint.h>

using namespace nvcuda;

#define NROWS 65536
#define HDIM  512
#define MD    128
#define PROTO 12
#define KR    1408
#define KRR   1024
#define KFN   1568
#define RSCALE 0.2f

typedef __nv_bfloat16 bf16;

// ---------------- scratch (device globals; allocation-free) ----------------
__device__ __align__(1024) __half g_A1 [(size_t)NROWS * KRR];
__device__ __align__(1024) __half g_B0 [(size_t)KRR * HDIM];
__device__ __align__(1024) __half g_B1 [(size_t)KRR * HDIM];
__device__ __align__(16)   float g_TS  [(size_t)2049 * HDIM];
__device__ __align__(16)   float g_TH  [(size_t)10 * HDIM];
__device__ __align__(16)   float g_TP  [(size_t)8 * HDIM];
__device__ __align__(16)   float g_H1  [(size_t)NROWS * HDIM];
__device__ __align__(1024) bf16  g_FEATSH[(size_t)NROWS * KFN];
__device__ __align__(16)   float g_H12 [(size_t)NROWS * 1024];
__device__ __align__(1024) bf16  g_HMUH[(size_t)NROWS * HDIM];
__device__ __align__(1024) bf16  g_HMGH[(size_t)NROWS * HDIM];
__device__ __align__(16)   float g_DELTA[(size_t)NROWS * HDIM];
__device__ __align__(16)   float g_GATE [(size_t)NROWS * HDIM];
__device__ __align__(1024) bf16  g_W1  [(size_t)KFN * 1024];
__device__ __align__(1024) bf16  g_W2MU[(size_t)HDIM * HDIM];
__device__ __align__(1024) bf16  g_W2MG[(size_t)HDIM * HDIM];
__device__ __align__(16)   float g_W2T [(size_t)PROTO * HDIM];
__device__ int g_count;
__device__ int g_LIST[NROWS];

// ---------------- helpers ----------------
__device__ __forceinline__ float gelu_exact(float x) {
    return 0.5f * x * (1.0f + erff(x * 0.70710678118654752440f));
}
__device__ __forceinline__ float warp_sum(float v) {
    #pragma unroll
    for (int o = 16; o; o >>= 1) v += __shfl_xor_sync(0xffffffffu, v, o);
    return v;
}
__device__ __forceinline__ double block_sum_128d(double v, double* sbuf) {
    #pragma unroll
    for (int o = 16; o; o >>= 1) v += __shfl_xor_sync(0xffffffffu, v, o);
    int w = threadIdx.x >> 5;
    if ((threadIdx.x & 31) == 0) sbuf[w] = v;
    __syncthreads();
    double r = sbuf[0] + sbuf[1] + sbuf[2] + sbuf[3];
    __syncthreads();
    return r;
}
__device__ __forceinline__ void twosum_acc(float& sum, float& comp, float v) {
    float s = sum + v;
    float z = s - sum;
    float e = (sum - (s - z)) + (v - z);
    sum = s;
    comp += e;
}
__device__ __forceinline__ void cp16(uint32_t dst, const void* src) {
    asm volatile("cp.async.cg.shared.global [%0], [%1], 16;" :: "r"(dst), "l"(src) : "memory");
}
__device__ __forceinline__ uint32_t smem_u32(const void* p) {
    uint32_t a;
    asm("{ .reg .u64 t; cvta.to.shared.u64 t, %1; cvt.u32.u64 %0, t; }" : "=r"(a) : "l"(p));
    return a;
}
#define CP_COMMIT() asm volatile("cp.async.commit_group;" ::: "memory")

__device__ __forceinline__ unsigned pack_bf2(float a, float b) {
    return ((unsigned)__bfloat16_as_ushort(__float2bfloat16_rn(b)) << 16)
         |  (unsigned)__bfloat16_as_ushort(__float2bfloat16_rn(a));
}
__device__ __forceinline__ void st_bf4(bf16* p, float4 v) {
    uint2 u;
    u.x = pack_bf2(v.x, v.y);
    u.y = pack_bf2(v.z, v.w);
    *reinterpret_cast<uint2*>(p) = u;
}

// ---------------- k_prep (unchanged) ------------------------------------------
__global__ void k_prep(const float* __restrict__ rw1, const float* __restrict__ rw2,
                       const float* __restrict__ muw1, const float* __restrict__ mgw1,
                       const float* __restrict__ muw2, const float* __restrict__ mgw2,
                       const float* __restrict__ se, const float* __restrict__ he,
                       const float* __restrict__ soe, const float* __restrict__ proto) {
    int gtid = blockIdx.x * blockDim.x + threadIdx.x;
    int gs = blockDim.x * gridDim.x;
    if (gtid == 0) g_count = 0;
    for (int i = gtid; i < KRR * HDIM; i += gs) {
        float v = rw1[i];
        __half h0 = __float2half_rn(v);
        __half h1 = __float2half_rn(v - __half2float(h0));
        g_B0[i] = h0; g_B1[i] = h1;
    }
    for (int i = gtid; i < 2049 * HDIM; i += gs) {
        int b = i >> 9, c = i & 511;
        float acc = 0.0f;
        for (int j = 0; j < MD; j++)
            acc = fmaf(se[b * MD + j], rw1[(size_t)(1024 + j) * HDIM + c], acc);
        g_TS[i] = acc;
    }
    for (int i = gtid; i < 10 * HDIM; i += gs) {
        int b = i >> 9, c = i & 511;
        float acc = 0.0f;
        for (int j = 0; j < MD; j++)
            acc = fmaf(he[b * MD + j], rw1[(size_t)(1152 + j) * HDIM + c], acc);
        g_TH[i] = acc;
    }
    for (int i = gtid; i < 8 * HDIM; i += gs) {
        int b = i >> 9, c = i & 511;
        float acc = 0.0f;
        for (int j = 0; j < MD; j++)
            acc = fmaf(soe[b * MD + j], rw1[(size_t)(1280 + j) * HDIM + c], acc);
        g_TP[i] = acc;
    }
    for (int i = gtid; i < 1536 * HDIM; i += gs) {
        int k = i >> 9, c = i & 511;
        int ok = (k < 512) ? k : k + 512;
        g_W1[(size_t)k * 1024 + c]       = __float2bfloat16_rn(muw1[(size_t)ok * HDIM + c]);
        g_W1[(size_t)k * 1024 + 512 + c] = __float2bfloat16_rn(mgw1[(size_t)ok * HDIM + c]);
    }
    for (int i = gtid; i < 32 * 1024; i += gs) {
        int kk = i >> 10, c = i & 1023;
        float acc = 0.0f;
        if (kk < PROTO) {
            if (c < 512) {
                for (int j = 0; j < 512; j++)
                    acc = fmaf(proto[kk * HDIM + j], muw1[(size_t)(512 + j) * HDIM + c], acc);
            } else {
                for (int j = 0; j < 512; j++)
                    acc = fmaf(proto[kk * HDIM + j], mgw1[(size_t)(512 + j) * HDIM + (c - 512)], acc);
            }
        }
        g_W1[(size_t)(1536 + kk) * 1024 + c] = __float2bfloat16_rn(acc);
    }
    for (int i = gtid; i < HDIM * HDIM; i += gs) {
        g_W2MU[i] = __float2bfloat16_rn(muw2[i]);
        g_W2MG[i] = __float2bfloat16_rn(mgw2[i]);
    }
    for (int i = gtid; i < PROTO * HDIM; i += gs) {
        int l = i / HDIM, c = i - l * HDIM;
        g_W2T[i] = rw2[(size_t)c * PROTO + l];
    }
}

// ---------------- gather -> fp16 (unchanged) ----------------------------------
__global__ void k_gather(const float* __restrict__ pair, const float* __restrict__ ep) {
    int row = blockIdx.x;
    const float4* pr = reinterpret_cast<const float4*>(&pair[(size_t)row * HDIM]);
    const float4* er = reinterpret_cast<const float4*>(&ep[(size_t)row * HDIM]);
    __half* dst = &g_A1[(size_t)row * KRR];
    for (int v = threadIdx.x; v < KRR / 4; v += blockDim.x) {
        float4 f = (v < 128) ? pr[v] : er[v - 128];
        uint2 u;
        u.x = ((unsigned)__half_as_ushort(__float2half_rn(f.y)) << 16)
            |  (unsigned)__half_as_ushort(__float2half_rn(f.x));
        u.y = ((unsigned)__half_as_ushort(__float2half_rn(f.w)) << 16)
            |  (unsigned)__half_as_ushort(__float2half_rn(f.z));
        *reinterpret_cast<uint2*>(dst + 4 * v) = u;
    }
}

// ---------------- router GEMM (unchanged, proven) -----------------------------
#define R2_A  5120
#define R2_B  4352
#define R2_ST (R2_A + 2 * R2_B)

__global__ void __launch_bounds__(256) gemm_router2(float* __restrict__ C) {
    extern __shared__ __align__(16) __half sm[];
    const int tid  = threadIdx.x;
    const int warp = tid >> 5;
    const int wr   = warp >> 1;
    const int wc   = warp & 1;
    const int m0 = blockIdx.y * 128;
    const int n0 = blockIdx.x * 128;
    const uint32_t smb = smem_u32(sm);

    wmma::fragment<wmma::accumulator, 16, 16, 16, float> acc[2][4];
    #pragma unroll
    for (int i = 0; i < 2; i++)
        #pragma unroll
        for (int j = 0; j < 4; j++) wmma::fill_fragment(acc[i][j], 0.0f);

    const __half* Ab = g_A1 + (size_t)m0 * KRR;

    auto load_stage = [&](int st, int kt) {
        uint32_t sb = smb + st * R2_ST * 2;
        #pragma unroll
        for (int q = 0; q < 2; q++) {
            int idx = tid + q * 256;
            int row = idx >> 2, c8 = (idx & 3) << 3;
            cp16(sb + row * 80 + c8 * 2, Ab + (size_t)row * KRR + kt + c8);
        }
        #pragma unroll
        for (int q = 0; q < 2; q++) {
            int idx = tid + q * 256;
            int row = idx >> 4, c8 = (idx & 15) << 3;
            cp16(sb + R2_A * 2 + row * 272 + c8 * 2,
                 g_B0 + (size_t)(kt + row) * HDIM + n0 + c8);
        }
        #pragma unroll
        for (int q = 0; q < 2; q++) {
            int idx = tid + q * 256;
            int row = idx >> 4, c8 = (idx & 15) << 3;
            cp16(sb + (R2_A + R2_B) * 2 + row * 272 + c8 * 2,
                 g_B1 + (size_t)(kt + row) * HDIM + n0 + c8);
        }
        CP_COMMIT();
    };

    load_stage(0, 0);
    load_stage(1, 32);

    const int nch = KRR / 32;
    for (int i = 0; i < nch; i++) {
        int s = i & 1;
        if (i == nch - 1) asm volatile("cp.async.wait_group 0;" ::: "memory");
        else              asm volatile("cp.async.wait_group 1;" ::: "memory");
        __syncthreads();
        const __half* As  = sm + s * R2_ST;
        const __half* B0s = As + R2_A;
        const __half* B1s = B0s + R2_B;
        #pragma unroll
        for (int ks = 0; ks < 32; ks += 16) {
            wmma::fragment<wmma::matrix_a, 16, 16, 16, __half, wmma::row_major> a0[2];
            wmma::fragment<wmma::matrix_b, 16, 16, 16, __half, wmma::row_major> b0[4], b1[4];
            #pragma unroll
            for (int ii = 0; ii < 2; ii++)
                wmma::load_matrix_sync(a0[ii], As + (wr * 32 + ii * 16) * 40 + ks, 40);
            #pragma unroll
            for (int jj = 0; jj < 4; jj++) {
                wmma::load_matrix_sync(b0[jj], B0s + ks * 136 + wc * 64 + jj * 16, 136);
                wmma::load_matrix_sync(b1[jj], B1s + ks * 136 + wc * 64 + jj * 16, 136);
            }
            #pragma unroll
            for (int ii = 0; ii < 2; ii++)
                #pragma unroll
                for (int jj = 0; jj < 4; jj++) {
                    wmma::mma_sync(acc[ii][jj], a0[ii], b0[jj], acc[ii][jj]);
                    wmma::mma_sync(acc[ii][jj], a0[ii], b1[jj], acc[ii][jj]);
                }
        }
        __syncthreads();
        if (i + 2 < nch) load_stage(s, (i + 2) * 32);
    }

    #pragma unroll
    for (int ii = 0; ii < 2; ii++)
        #pragma unroll
        for (int jj = 0; jj < 4; jj++) {
            float* Cp = C + (size_t)(m0 + wr * 32 + ii * 16) * HDIM + n0 + wc * 64 + jj * 16;
            wmma::store_matrix_sync(Cp, acc[ii][jj], HDIM, wmma::mem_row_major);
        }
}

// ---------------- bf16 GEMM (unchanged, proven) -------------------------------
__global__ void __launch_bounds__(256) gemm_bf16(const bf16* __restrict__ A,
                                                 const bf16* __restrict__ B,
                                                 float* __restrict__ C,
                                                 int K, int NC) {
    __shared__ __align__(16) bf16 As[2][128][40];
    __shared__ __align__(16) bf16 Bs[2][32][136];
    const int m0 = blockIdx.y * 128;
    const int n0 = blockIdx.x * 128;
    const int tid  = threadIdx.x;
    const int warp = tid >> 5;
    const int wr   = warp >> 1;
    const int wc   = warp & 1;
    const uint32_t sa = smem_u32(&As[0][0][0]);
    const uint32_t sbb = smem_u32(&Bs[0][0][0]);

    wmma::fragment<wmma::accumulator, 16, 16, 16, float> acc[2][4];
    #pragma unroll
    for (int i = 0; i < 2; i++)
        #pragma unroll
        for (int j = 0; j < 4; j++) wmma::fill_fragment(acc[i][j], 0.0f);

    auto load_stage = [&](int st, int kt) {
        uint32_t ab = sa + st * (128 * 40 * 2);
        uint32_t bb = sbb + st * (32 * 136 * 2);
        #pragma unroll
        for (int q = 0; q < 2; q++) {
            int idx = tid + q * 256;
            int row = idx >> 2, c8 = (idx & 3) << 3;
            cp16(ab + row * 80 + c8 * 2, A + (size_t)(m0 + row) * K + kt + c8);
        }
        #pragma unroll
        for (int q = 0; q < 2; q++) {
            int idx = tid + q * 256;
            int row = idx >> 4, c8 = (idx & 15) << 3;
            cp16(bb + row * 272 + c8 * 2, B + (size_t)(kt + row) * NC + n0 + c8);
        }
        CP_COMMIT();
    };

    load_stage(0, 0);
    load_stage(1, 32);

    const int nch = K / 32;
    for (int i = 0; i < nch; i++) {
        int s = i & 1;
        if (i == nch - 1) asm volatile("cp.async.wait_group 0;" ::: "memory");
        else              asm volatile("cp.async.wait_group 1;" ::: "memory");
        __syncthreads();
        #pragma unroll
        for (int ks = 0; ks < 32; ks += 16) {
            wmma::fragment<wmma::matrix_a, 16, 16, 16, bf16, wmma::row_major> af[2];
            wmma::fragment<wmma::matrix_b, 16, 16, 16, bf16, wmma::row_major> bfr[4];
            #pragma unroll
            for (int ii = 0; ii < 2; ii++)
                wmma::load_matrix_sync(af[ii], &As[s][wr * 32 + ii * 16][ks], 40);
            #pragma unroll
            for (int jj = 0; jj < 4; jj++)
                wmma::load_matrix_sync(bfr[jj], &Bs[s][ks][wc * 64 + jj * 16], 136);
            #pragma unroll
            for (int ii = 0; ii < 2; ii++)
                #pragma unroll
                for (int jj = 0; jj < 4; jj++)
                    wmma::mma_sync(acc[ii][jj], af[ii], bfr[jj], acc[ii][jj]);
        }
        __syncthreads();
        if (i + 2 < nch) load_stage(s, (i + 2) * 32);
    }

    #pragma unroll
    for (int i = 0; i < 2; i++)
        #pragma unroll
        for (int j = 0; j < 4; j++) {
            float* Cp = C + (size_t)(m0 + wr * 32 + i * 16) * NC + n0 + wc * 64 + j * 16;
            wmma::store_matrix_sync(Cp, acc[i][j], NC, wmma::mem_row_major);
        }
}

// ---------------- router2: warp-per-row, zero syncthreads ---------------------
__global__ void __launch_bounds__(256) k_router2(
        const float* __restrict__ ep,
        const int* __restrict__ sid, const int* __restrict__ hc,
        const int* __restrict__ ps,
        const float* __restrict__ rb1, const float* __restrict__ rlg,
        const float* __restrict__ rlb,
        const float* __restrict__ b2, const float* __restrict__ proto,
        float* __restrict__ outC, float* __restrict__ outW) {
    const int warp = threadIdx.x >> 5, lane = threadIdx.x & 31;
    const int row = blockIdx.x * 8 + warp;
    int sI = min(max(sid[row], 0), 2048);
    int hI = min(max(hc[row], 0), 9);
    int pI = min(max(ps[row], 0), 7);
    const float4* h4p  = reinterpret_cast<const float4*>(&g_H1[(size_t)row * HDIM]);
    const float4* b4p  = reinterpret_cast<const float4*>(rb1);
    const float4* ts4p = reinterpret_cast<const float4*>(&g_TS[(size_t)sI * HDIM]);
    const float4* th4p = reinterpret_cast<const float4*>(&g_TH[(size_t)hI * HDIM]);
    const float4* tp4p = reinterpret_cast<const float4*>(&g_TP[(size_t)pI * HDIM]);
    float4 pre[4];
    float s1 = 0.0f, s2 = 0.0f;
    #pragma unroll
    for (int q = 0; q < 4; q++) {
        int c4 = lane + 32 * q;
        float4 h = h4p[c4], b = b4p[c4], ts = ts4p[c4], th = th4p[c4], tp = tp4p[c4];
        pre[q].x = h.x + b.x + ts.x + th.x + tp.x;
        pre[q].y = h.y + b.y + ts.y + th.y + tp.y;
        pre[q].z = h.z + b.z + ts.z + th.z + tp.z;
        pre[q].w = h.w + b.w + ts.w + th.w + tp.w;
        s1 += pre[q].x + pre[q].y + pre[q].z + pre[q].w;
        s2 += pre[q].x * pre[q].x + pre[q].y * pre[q].y
            + pre[q].z * pre[q].z + pre[q].w * pre[q].w;
    }
    s1 = warp_sum(s1);
    s2 = warp_sum(s2);
    float mean = s1 * (1.0f / 512.0f);
    float var  = s2 * (1.0f / 512.0f) - mean * mean;
    float rs = rsqrtf(var + 1e-5f);
    const float4* g4p  = reinterpret_cast<const float4*>(rlg);
    const float4* be4p = reinterpret_cast<const float4*>(rlb);
    float4 hv[4];
    #pragma unroll
    for (int q = 0; q < 4; q++) {
        int c4 = lane + 32 * q;
        float4 g = g4p[c4], be = be4p[c4];
        hv[q].x = gelu_exact((pre[q].x - mean) * rs * g.x + be.x);
        hv[q].y = gelu_exact((pre[q].y - mean) * rs * g.y + be.y);
        hv[q].z = gelu_exact((pre[q].z - mean) * rs * g.z + be.z);
        hv[q].w = gelu_exact((pre[q].w - mean) * rs * g.w + be.w);
    }
    // logits: 12 register dots + warp reduce
    float lg[PROTO];
    #pragma unroll
    for (int l = 0; l < PROTO; l++) {
        const float4* wl = reinterpret_cast<const float4*>(&g_W2T[l * HDIM]);
        float sa = 0.0f;
        #pragma unroll
        for (int q = 0; q < 4; q++) {
            float4 w = wl[lane + 32 * q];
            sa = fmaf(hv[q].x, w.x, sa);
            sa = fmaf(hv[q].y, w.y, sa);
            sa = fmaf(hv[q].z, w.z, sa);
            sa = fmaf(hv[q].w, w.w, sa);
        }
        lg[l] = warp_sum(sa);
    }
    // lane 0: bias, flag, softmax, top-4, renorm
    float sw[PROTO];
    if (lane == 0) {
        float w[PROTO];
        #pragma unroll
        for (int i = 0; i < PROTO; i++) w[i] = lg[i] + b2[i];
        float v[PROTO];
        #pragma unroll
        for (int i = 0; i < PROTO; i++) v[i] = w[i];
        float top5[5];
        #pragma unroll
        for (int k = 0; k < 5; k++) {
            int bi = 0; float bv = -1e30f;
            #pragma unroll
            for (int i = 0; i < PROTO; i++)
                if (v[i] > bv) { bv = v[i]; bi = i; }
            top5[k] = bv; v[bi] = -1e30f;
        }
        if (top5[3] - top5[4] < 2e-3f) {
            int pos = atomicAdd(&g_count, 1);
            g_LIST[pos] = row;
        }
        float mx = top5[0];
        float ssum = 0.0f;
        #pragma unroll
        for (int i = 0; i < PROTO; i++) { w[i] = expf(w[i] - mx); ssum += w[i]; }
        float inv = 1.0f / ssum;
        #pragma unroll
        for (int i = 0; i < PROTO; i++) w[i] *= inv;
        bool sel[PROTO];
        #pragma unroll
        for (int i = 0; i < PROTO; i++) sel[i] = false;
        for (int k = 0; k < 4; k++) {
            int bi = -1; float bv = -1e30f;
            #pragma unroll
            for (int i = 0; i < PROTO; i++)
                if (!sel[i] && w[i] > bv) { bv = w[i]; bi = i; }
            sel[bi] = true;
        }
        float s22 = 0.0f;
        #pragma unroll
        for (int i = 0; i < PROTO; i++) { float vv = sel[i] ? w[i] : 0.0f; sw[i] = vv; s22 += vv; }
        float d = 1.0f / fmaxf(s22, 1e-6f);
        #pragma unroll
        for (int i = 0; i < PROTO; i++) sw[i] *= d;
    }
    // broadcast sw to all lanes
    #pragma unroll
    for (int i = 0; i < PROTO; i++) sw[i] = __shfl_sync(0xffffffffu, sw[i], 0);
    // outW (lane 0 writes 12 floats)
    if (lane == 0) {
        float* ow = &outW[(size_t)row * PROTO];
        #pragma unroll
        for (int i = 0; i < PROTO; i++) ow[i] = sw[i];
    }
    // ctx + feats
    const float4* e4p = reinterpret_cast<const float4*>(&ep[(size_t)row * HDIM]);
    float4* oc4p = reinterpret_cast<float4*>(&outC[(size_t)row * HDIM]);
    bf16* frow = &g_FEATSH[(size_t)row * KFN];
    #pragma unroll
    for (int q = 0; q < 4; q++) {
        int c4 = lane + 32 * q;
        float4 c = make_float4(0.f, 0.f, 0.f, 0.f);
        #pragma unroll
        for (int p = 0; p < PROTO; p++) {
            float wv = sw[p];
            float4 pv = reinterpret_cast<const float4*>(&proto[p * HDIM])[c4];
            c.x = fmaf(wv, pv.x, c.x);
            c.y = fmaf(wv, pv.y, c.y);
            c.z = fmaf(wv, pv.z, c.z);
            c.w = fmaf(wv, pv.w, c.w);
        }
        float4 e = e4p[c4];
        oc4p[c4] = c;
        st_bf4(frow + 4 * c4, e);
        st_bf4(frow + 512 + 4 * c4, make_float4(fabsf(e.x - c.x), fabsf(e.y - c.y),
                                                fabsf(e.z - c.z), fabsf(e.w - c.w)));
        st_bf4(frow + 1024 + 4 * c4, make_float4(e.x * c.x, e.y * c.y,
                                                 e.z * c.z, e.w * c.w));
    }
    if (lane < 16) {
        float a = (lane * 2 < PROTO)     ? sw[lane * 2]     : 0.0f;
        float b = (lane * 2 + 1 < PROTO) ? sw[lane * 2 + 1] : 0.0f;
        reinterpret_cast<unsigned*>(frow + 1536)[lane] = pack_bf2(a, b);
    }
}

// ---------------- rescue (exact fp32 path, unchanged) -------------------------
__global__ void __launch_bounds__(128) k_rescue(
        const float* __restrict__ pair, const float* __restrict__ ep,
        const int* __restrict__ sid, const int* __restrict__ hc, const int* __restrict__ ps,
        const float* __restrict__ se, const float* __restrict__ he, const float* __restrict__ soe,
        const float* __restrict__ rw1, const float* __restrict__ rb1,
        const float* __restrict__ rlg, const float* __restrict__ rlb,
        const float* __restrict__ b2, const float* __restrict__ proto,
        float* __restrict__ outC, float* __restrict__ outW) {
    __shared__ float sa[KR];
    __shared__ float shd[HDIM];
    __shared__ double dbuf[4];
    __shared__ float sl[PROTO];
    __shared__ float sw[PROTO];
    int t = threadIdx.x, warp = t >> 5, lane = t & 31;
    int cnt = g_count;
    for (int li = blockIdx.x; li < cnt; li += gridDim.x) {
        int row = g_LIST[li];
        int s = min(max(sid[row], 0), 2048);
        int h = min(max(hc[row], 0), 9);
        int p = min(max(ps[row], 0), 7);
        const float* pr = &pair[(size_t)row * HDIM];
        const float* er = &ep[(size_t)row * HDIM];
        for (int k = t; k < KR; k += 128) {
            float v;
            if      (k < 512)  v = pr[k];
            else if (k < 1024) v = er[k - 512];
            else if (k < 1152) v = se[s * MD + (k - 1024)];
            else if (k < 1280) v = he[h * MD + (k - 1152)];
            else               v = soe[p * MD + (k - 1280)];
            sa[k] = v;
        }
        __syncthreads();
        float hs[4], hcmp[4];
        #pragma unroll
        for (int j = 0; j < 4; j++) { hs[j] = 0.0f; hcmp[j] = 0.0f; }
        for (int k = 0; k < KR; k++) {
            float a = sa[k];
            const float* wr = &rw1[(size_t)k * HDIM];
            #pragma unroll
            for (int j = 0; j < 4; j++) {
                int c = t + j * 128;
                float w = wr[c];
                float pp = a * w;
                float pe = fmaf(a, w, -pp);
                twosum_acc(hs[j], hcmp[j], pp);
                hcmp[j] += pe;
            }
        }
        float pre[4];
        double msum = 0.0;
        #pragma unroll
        for (int j = 0; j < 4; j++) {
            pre[j] = (hs[j] + hcmp[j]) + rb1[t + j * 128];
            msum += (double)pre[j];
        }
        double mean = block_sum_128d(msum, dbuf) * (1.0 / 512.0);
        double vsum = 0.0;
        #pragma unroll
        for (int j = 0; j < 4; j++) {
            double e0 = (double)pre[j] - mean;
            vsum += e0 * e0;
        }
        double var = block_sum_128d(vsum, dbuf) * (1.0 / 512.0);
        float rs = (float)(1.0 / sqrt(var + 1e-5));
        #pragma unroll
        for (int j = 0; j < 4; j++) {
            int c = t + j * 128;
            shd[c] = gelu_exact((float)((double)pre[j] - mean) * rs * rlg[c] + rlb[c]);
        }
        __syncthreads();
        for (int l = warp; l < PROTO; l += 4) {
            float ss = 0.0f, cmp = 0.0f;
            const float* wl = &g_W2T[l * HDIM];
            for (int c = lane; c < HDIM; c += 32) {
                float a = shd[c], w = wl[c];
                float pp = a * w;
                float pe = fmaf(a, w, -pp);
                twosum_acc(ss, cmp, pp);
                cmp += pe;
            }
            #pragma unroll
            for (int o = 16; o; o >>= 1) {
                ss  += __shfl_xor_sync(0xffffffffu, ss, o);
                cmp += __shfl_xor_sync(0xffffffffu, cmp, o);
            }
            if (lane == 0) sl[l] = (ss + cmp) + b2[l];
        }
        __syncthreads();
        if (t == 0) {
            float w[PROTO];
            float mx = -1e30f;
            #pragma unroll
            for (int i = 0; i < PROTO; i++) mx = fmaxf(mx, sl[i]);
            float ssum = 0.0f;
            #pragma unroll
            for (int i = 0; i < PROTO; i++) { w[i] = expf(sl[i] - mx); ssum += w[i]; }
            float inv = 1.0f / ssum;
            #pragma unroll
            for (int i = 0; i < PROTO; i++) w[i] *= inv;
            bool sel[PROTO];
            #pragma unroll
            for (int i = 0; i < PROTO; i++) sel[i] = false;
            for (int k = 0; k < 4; k++) {
                int bi = -1; float bv = -1e30f;
                #pragma unroll
                for (int i = 0; i < PROTO; i++)
                    if (!sel[i] && w[i] > bv) { bv = w[i]; bi = i; }
                sel[bi] = true;
            }
            float s2 = 0.0f;
            #pragma unroll
            for (int i = 0; i < PROTO; i++) { float vv = sel[i] ? w[i] : 0.0f; sw[i] = vv; s2 += vv; }
            float d = 1.0f / fmaxf(s2, 1e-6f);
            #pragma unroll
            for (int i = 0; i < PROTO; i++) sw[i] *= d;
        }
        __syncthreads();
        if (t < PROTO) outW[(size_t)row * PROTO + t] = sw[t];
        bf16* frow = &g_FEATSH[(size_t)row * KFN];
        for (int j = t; j < HDIM; j += 128) {
            float c = 0.0f;
            #pragma unroll
            for (int pp = 0; pp < PROTO; pp++) c += sw[pp] * proto[pp * HDIM + j];
            float e = er[j];
            outC[(size_t)row * HDIM + j] = c;
            frow[j]        = __float2bfloat16_rn(e);
            frow[512 + j]  = __float2bfloat16_rn(fabsf(e - c));
            frow[1024 + j] = __float2bfloat16_rn(e * c);
        }
        if (t < 32) frow[1536 + t] = __float2bfloat16_rn(t < PROTO ? sw[t] : 0.0f);
        __syncthreads();
    }
}

// ---------------- activations: warp-per-row -----------------------------------
__global__ void __launch_bounds__(256) k_act(
        const float* __restrict__ b_mu, const float* __restrict__ g_mu,
        const float* __restrict__ be_mu, const float* __restrict__ b_mg) {
    const int warp = threadIdx.x >> 5, lane = threadIdx.x & 31;
    const int row = blockIdx.x * 8 + warp;
    const float4* h12 = reinterpret_cast<const float4*>(&g_H12[(size_t)row * 1024]);
    const float4* bm4 = reinterpret_cast<const float4*>(b_mu);
    float4 m[4];
    float s1 = 0.0f, s2 = 0.0f;
    #pragma unroll
    for (int q = 0; q < 4; q++) {
        int c4 = lane + 32 * q;
        float4 h = h12[c4], b = bm4[c4];
        m[q].x = h.x + b.x; m[q].y = h.y + b.y;
        m[q].z = h.z + b.z; m[q].w = h.w + b.w;
        s1 += m[q].x + m[q].y + m[q].z + m[q].w;
        s2 += m[q].x * m[q].x + m[q].y * m[q].y + m[q].z * m[q].z + m[q].w * m[q].w;
    }
    s1 = warp_sum(s1);
    s2 = warp_sum(s2);
    float mean = s1 * (1.0f / 512.0f);
    float var  = s2 * (1.0f / 512.0f) - mean * mean;
    float rs = rsqrtf(var + 1e-5f);
    const float4* g4p  = reinterpret_cast<const float4*>(g_mu);
    const float4* be4p = reinterpret_cast<const float4*>(be_mu);
    const float4* bg4p = reinterpret_cast<const float4*>(b_mg);
    bf16* xm = &g_HMUH[(size_t)row * HDIM];
    bf16* xg = &g_HMGH[(size_t)row * HDIM];
    #pragma unroll
    for (int q = 0; q < 4; q++) {
        int c4 = lane + 32 * q;
        float4 g = g4p[c4], be = be4p[c4];
        float4 o;
        o.x = gelu_exact((m[q].x - mean) * rs * g.x + be.x);
        o.y = gelu_exact((m[q].y - mean) * rs * g.y + be.y);
        o.z = gelu_exact((m[q].z - mean) * rs * g.z + be.z);
        o.w = gelu_exact((m[q].w - mean) * rs * g.w + be.w);
        st_bf4(xm + 4 * c4, o);
        float4 gg = h12[128 + c4], bg = bg4p[c4];
        float4 og;
        og.x = gelu_exact(gg.x + bg.x);
        og.y = gelu_exact(gg.y + bg.y);
        og.z = gelu_exact(gg.z + bg.z);
        og.w = gelu_exact(gg.w + bg.w);
        st_bf4(xg + 4 * c4, og);
    }
}

// ---------------- final: warp-per-row -----------------------------------------
__global__ void __launch_bounds__(256) k_final(
        const float* __restrict__ ep, const float* __restrict__ mub2,
        const float* __restrict__ mgb2, const float* __restrict__ ng,
        const float* __restrict__ nb, float* __restrict__ outU) {
    const int warp = threadIdx.x >> 5, lane = threadIdx.x & 31;
    const int row = blockIdx.x * 8 + warp;
    const float4* e4p  = reinterpret_cast<const float4*>(&ep[(size_t)row * HDIM]);
    const float4* d4p  = reinterpret_cast<const float4*>(&g_DELTA[(size_t)row * HDIM]);
    const float4* gp4p = reinterpret_cast<const float4*>(&g_GATE[(size_t)row * HDIM]);
    const float4* db4p = reinterpret_cast<const float4*>(mub2);
    const float4* gb4p = reinterpret_cast<const float4*>(mgb2);
    float4 u[4];
    float s1 = 0.0f, s2 = 0.0f;
    #pragma unroll
    for (int q = 0; q < 4; q++) {
        int c4 = lane + 32 * q;
        float4 e = e4p[c4], d = d4p[c4], gp = gp4p[c4], db = db4p[c4], gb = gb4p[c4];
        u[q].x = e.x + RSCALE * (1.0f / (1.0f + expf(-(gp.x + gb.x)))) * (d.x + db.x);
        u[q].y = e.y + RSCALE * (1.0f / (1.0f + expf(-(gp.y + gb.y)))) * (d.y + db.y);
        u[q].z = e.z + RSCALE * (1.0f / (1.0f + expf(-(gp.z + gb.z)))) * (d.z + db.z);
        u[q].w = e.w + RSCALE * (1.0f / (1.0f + expf(-(gp.w + gb.w)))) * (d.w + db.w);
        s1 += u[q].x + u[q].y + u[q].z + u[q].w;
        s2 += u[q].x * u[q].x + u[q].y * u[q].y + u[q].z * u[q].z + u[q].w * u[q].w;
    }
    s1 = warp_sum(s1);
    s2 = warp_sum(s2);
    float mean = s1 * (1.0f / 512.0f);
    float var  = s2 * (1.0f / 512.0f) - mean * mean;
    float rs = rsqrtf(var + 1e-5f);
    const float4* g4p = reinterpret_cast<const float4*>(ng);
    const float4* b4p = reinterpret_cast<const float4*>(nb);
    float4* ou = reinterpret_cast<float4*>(&outU[(size_t)row * HDIM]);
    #pragma unroll
    for (int q = 0; q < 4; q++) {
        int c4 = lane + 32 * q;
        float4 g = g4p[c4], b = b4p[c4];
        float4 o;
        o.x = (u[q].x - mean) * rs * g.x + b.x;
        o.y = (u[q].y - mean) * rs * g.y + b.y;
        o.z = (u[q].z - mean) * rs * g.z + b.z;
        o.w = (u[q].w - mean) * rs * g.w + b.w;
        ou[c4] = o;
    }
}

// ---------------- launch ----------------
extern "C" void kernel_launch(void* const* d_in, const int* in_sizes, int n_in,
                              void* d_out, int out_size) {
    const float* pair = (const float*)d_in[0];
    const float* ep   = (const float*)d_in[1];
    const int*   sid  = (const int*)d_in[2];
    const int*   hc   = (const int*)d_in[3];
    const int*   ps   = (const int*)d_in[4];
    const float* se   = (const float*)d_in[5];
    const float* he   = (const float*)d_in[6];
    const float* soe  = (const float*)d_in[7];
    const float* proto= (const float*)d_in[8];
    const float* rw1  = (const float*)d_in[9];
    const float* rb1  = (const float*)d_in[10];
    const float* rlg  = (const float*)d_in[11];
    const float* rlb  = (const float*)d_in[12];
    const float* rw2  = (const float*)d_in[13];
    const float* rb2  = (const float*)d_in[14];
    const float* muw1 = (const float*)d_in[15];
    const float* mub1 = (const float*)d_in[16];
    const float* mulg = (const float*)d_in[17];
    const float* mulb = (const float*)d_in[18];
    const float* muw2 = (const float*)d_in[19];
    const float* mub2 = (const float*)d_in[20];
    const float* mgw1 = (const float*)d_in[21];
    const float* mgb1 = (const float*)d_in[22];
    const float* mgw2 = (const float*)d_in[23];
    const float* mgb2 = (const float*)d_in[24];
    const float* ng   = (const float*)d_in[25];
    const float* nb   = (const float*)d_in[26];

    float* outU = (float*)d_out;
    float* outC = outU + (size_t)NROWS * HDIM;
    float* outW = outC + (size_t)NROWS * HDIM;

    float *pH1, *pH12, *pDELTA, *pGATE;
    bf16 *pFEATSH, *pHMUH, *pHMGH, *pW1, *pW2MU, *pW2MG;
    cudaGetSymbolAddress((void**)&pH1,     g_H1);
    cudaGetSymbolAddress((void**)&pH12,    g_H12);
    cudaGetSymbolAddress((void**)&pDELTA,  g_DELTA);
    cudaGetSymbolAddress((void**)&pGATE,   g_GATE);
    cudaGetSymbolAddress((void**)&pFEATSH, g_FEATSH);
    cudaGetSymbolAddress((void**)&pHMUH,   g_HMUH);
    cudaGetSymbolAddress((void**)&pHMGH,   g_HMGH);
    cudaGetSymbolAddress((void**)&pW1,     g_W1);
    cudaGetSymbolAddress((void**)&pW2MU,   g_W2MU);
    cudaGetSymbolAddress((void**)&pW2MG,   g_W2MG);

    static bool attr_set = false;
    if (!attr_set) {
        cudaFuncSetAttribute(gemm_router2, cudaFuncAttributeMaxDynamicSharedMemorySize,
                             2 * R2_ST * 2 + 256);
        attr_set = true;
    }

    k_prep<<<4096, 256>>>(rw1, rw2, muw1, mgw1, muw2, mgw2, se, he, soe, proto);
    k_gather<<<NROWS, 128>>>(pair, ep);
    {
        dim3 grid(HDIM / 128, NROWS / 128);
        gemm_router2<<<grid, 256, 2 * R2_ST * 2 + 256>>>(pH1);
    }
    k_router2<<<NROWS / 8, 256>>>(ep, sid, hc, ps, rb1, rlg, rlb, rb2, proto, outC, outW);
    k_rescue<<<2048, 128>>>(pair, ep, sid, hc, ps, se, he, soe,
                            rw1, rb1, rlg, rlb, rb2, proto, outC, outW);
    {
        dim3 grid(1024 / 128, NROWS / 128);
        gemm_bf16<<<grid, 256>>>(pFEATSH, pW1, pH12, KFN, 1024);
    }
    k_act<<<NROWS / 8, 256>>>(mub1, mulg, mulb, mgb1);
    {
        dim3 grid(HDIM / 128, NROWS / 128);
        gemm_bf16<<<grid, 256>>>(pHMUH, pW2MU, pDELTA, HDIM, HDIM);
        gemm_bf16<<<grid, 256>>>(pHMGH, pW2MG, pGATE, HDIM, HDIM);
    }
    k_final<<<NROWS / 8, 256>>>(ep, mub2, mgb2, ng, nb, outU);
}

// round 13
// speedup vs baseline: 1.0523x; 1.0523x over previous
#include <cuda_runtime.h>
#include <cuda_bf16.h>
#include <cuda_fp16.h>
#include <mma.h>
#include <math.h>
#include <stdint.h>

using namespace nvcuda;

#define NROWS 65536
#define HDIM  512
#define MD    128
#define PROTO 12
#define KR    1408
#define KRR   1024
#define KFN   1568
#define RSCALE 0.2f

typedef __nv_bfloat16 bf16;

// ---------------- scratch (device globals; allocation-free) ----------------
__device__ __align__(1024) __half g_A1 [(size_t)NROWS * KRR];
__device__ __align__(1024) __half g_B0 [(size_t)KRR * HDIM];
__device__ __align__(1024) __half g_B1 [(size_t)KRR * HDIM];
__device__ __align__(16)   float g_TS  [(size_t)2049 * HDIM];
__device__ __align__(16)   float g_TH  [(size_t)10 * HDIM];
__device__ __align__(16)   float g_TP  [(size_t)8 * HDIM];
__device__ __align__(16)   float g_H1  [(size_t)NROWS * HDIM];
__device__ __align__(1024) bf16  g_FEATSH[(size_t)NROWS * KFN];
__device__ __align__(16)   float g_H12 [(size_t)NROWS * 1024];
__device__ __align__(1024) bf16  g_HMUH[(size_t)NROWS * HDIM];
__device__ __align__(1024) bf16  g_HMGH[(size_t)NROWS * HDIM];
__device__ __align__(16)   float g_DELTA[(size_t)NROWS * HDIM];
__device__ __align__(16)   float g_GATE [(size_t)NROWS * HDIM];
__device__ __align__(1024) bf16  g_W1  [(size_t)KFN * 1024];
__device__ __align__(1024) bf16  g_W2MU[(size_t)HDIM * HDIM];
__device__ __align__(1024) bf16  g_W2MG[(size_t)HDIM * HDIM];
__device__ __align__(16)   float g_W2T [(size_t)PROTO * HDIM];
__device__ int g_count;
__device__ int g_LIST[NROWS];

// ---------------- helpers ----------------
__device__ __forceinline__ float gelu_exact(float x) {
    return 0.5f * x * (1.0f + erff(x * 0.70710678118654752440f));
}
__device__ __forceinline__ float warp_sum(float v) {
    #pragma unroll
    for (int o = 16; o; o >>= 1) v += __shfl_xor_sync(0xffffffffu, v, o);
    return v;
}
__device__ __forceinline__ double block_sum_128d(double v, double* sbuf) {
    #pragma unroll
    for (int o = 16; o; o >>= 1) v += __shfl_xor_sync(0xffffffffu, v, o);
    int w = threadIdx.x >> 5;
    if ((threadIdx.x & 31) == 0) sbuf[w] = v;
    __syncthreads();
    double r = sbuf[0] + sbuf[1] + sbuf[2] + sbuf[3];
    __syncthreads();
    return r;
}
__device__ __forceinline__ void twosum_acc(float& sum, float& comp, float v) {
    float s = sum + v;
    float z = s - sum;
    float e = (sum - (s - z)) + (v - z);
    sum = s;
    comp += e;
}
__device__ __forceinline__ void cp16(uint32_t dst, const void* src) {
    asm volatile("cp.async.cg.shared.global [%0], [%1], 16;" :: "r"(dst), "l"(src) : "memory");
}
__device__ __forceinline__ uint32_t smem_u32(const void* p) {
    uint32_t a;
    asm("{ .reg .u64 t; cvta.to.shared.u64 t, %1; cvt.u32.u64 %0, t; }" : "=r"(a) : "l"(p));
    return a;
}
#define CP_COMMIT() asm volatile("cp.async.commit_group;" ::: "memory")
#define CP_WAIT(rem) do { \
    if ((rem) >= 2)      asm volatile("cp.async.wait_group 2;" ::: "memory"); \
    else if ((rem) == 1) asm volatile("cp.async.wait_group 1;" ::: "memory"); \
    else                 asm volatile("cp.async.wait_group 0;" ::: "memory"); \
} while (0)

__device__ __forceinline__ unsigned pack_bf2(float a, float b) {
    return ((unsigned)__bfloat16_as_ushort(__float2bfloat16_rn(b)) << 16)
         |  (unsigned)__bfloat16_as_ushort(__float2bfloat16_rn(a));
}
__device__ __forceinline__ void st_bf4(bf16* p, float4 v) {
    uint2 u;
    u.x = pack_bf2(v.x, v.y);
    u.y = pack_bf2(v.z, v.w);
    *reinterpret_cast<uint2*>(p) = u;
}

// ---------------- k_prep (unchanged) ------------------------------------------
__global__ void k_prep(const float* __restrict__ rw1, const float* __restrict__ rw2,
                       const float* __restrict__ muw1, const float* __restrict__ mgw1,
                       const float* __restrict__ muw2, const float* __restrict__ mgw2,
                       const float* __restrict__ se, const float* __restrict__ he,
                       const float* __restrict__ soe, const float* __restrict__ proto) {
    int gtid = blockIdx.x * blockDim.x + threadIdx.x;
    int gs = blockDim.x * gridDim.x;
    if (gtid == 0) g_count = 0;
    for (int i = gtid; i < KRR * HDIM; i += gs) {
        float v = rw1[i];
        __half h0 = __float2half_rn(v);
        __half h1 = __float2half_rn(v - __half2float(h0));
        g_B0[i] = h0; g_B1[i] = h1;
    }
    for (int i = gtid; i < 2049 * HDIM; i += gs) {
        int b = i >> 9, c = i & 511;
        float acc = 0.0f;
        for (int j = 0; j < MD; j++)
            acc = fmaf(se[b * MD + j], rw1[(size_t)(1024 + j) * HDIM + c], acc);
        g_TS[i] = acc;
    }
    for (int i = gtid; i < 10 * HDIM; i += gs) {
        int b = i >> 9, c = i & 511;
        float acc = 0.0f;
        for (int j = 0; j < MD; j++)
            acc = fmaf(he[b * MD + j], rw1[(size_t)(1152 + j) * HDIM + c], acc);
        g_TH[i] = acc;
    }
    for (int i = gtid; i < 8 * HDIM; i += gs) {
        int b = i >> 9, c = i & 511;
        float acc = 0.0f;
        for (int j = 0; j < MD; j++)
            acc = fmaf(soe[b * MD + j], rw1[(size_t)(1280 + j) * HDIM + c], acc);
        g_TP[i] = acc;
    }
    for (int i = gtid; i < 1536 * HDIM; i += gs) {
        int k = i >> 9, c = i & 511;
        int ok = (k < 512) ? k : k + 512;
        g_W1[(size_t)k * 1024 + c]       = __float2bfloat16_rn(muw1[(size_t)ok * HDIM + c]);
        g_W1[(size_t)k * 1024 + 512 + c] = __float2bfloat16_rn(mgw1[(size_t)ok * HDIM + c]);
    }
    for (int i = gtid; i < 32 * 1024; i += gs) {
        int kk = i >> 10, c = i & 1023;
        float acc = 0.0f;
        if (kk < PROTO) {
            if (c < 512) {
                for (int j = 0; j < 512; j++)
                    acc = fmaf(proto[kk * HDIM + j], muw1[(size_t)(512 + j) * HDIM + c], acc);
            } else {
                for (int j = 0; j < 512; j++)
                    acc = fmaf(proto[kk * HDIM + j], mgw1[(size_t)(512 + j) * HDIM + (c - 512)], acc);
            }
        }
        g_W1[(size_t)(1536 + kk) * 1024 + c] = __float2bfloat16_rn(acc);
    }
    for (int i = gtid; i < HDIM * HDIM; i += gs) {
        g_W2MU[i] = __float2bfloat16_rn(muw2[i]);
        g_W2MG[i] = __float2bfloat16_rn(mgw2[i]);
    }
    for (int i = gtid; i < PROTO * HDIM; i += gs) {
        int l = i / HDIM, c = i - l * HDIM;
        g_W2T[i] = rw2[(size_t)c * PROTO + l];
    }
}

// ---------------- gather -> fp16 (unchanged) ----------------------------------
__global__ void k_gather(const float* __restrict__ pair, const float* __restrict__ ep) {
    int row = blockIdx.x;
    const float4* pr = reinterpret_cast<const float4*>(&pair[(size_t)row * HDIM]);
    const float4* er = reinterpret_cast<const float4*>(&ep[(size_t)row * HDIM]);
    __half* dst = &g_A1[(size_t)row * KRR];
    for (int v = threadIdx.x; v < KRR / 4; v += blockDim.x) {
        float4 f = (v < 128) ? pr[v] : er[v - 128];
        uint2 u;
        u.x = ((unsigned)__half_as_ushort(__float2half_rn(f.y)) << 16)
            |  (unsigned)__half_as_ushort(__float2half_rn(f.x));
        u.y = ((unsigned)__half_as_ushort(__float2half_rn(f.w)) << 16)
            |  (unsigned)__half_as_ushort(__float2half_rn(f.z));
        *reinterpret_cast<uint2*>(dst + 4 * v) = u;
    }
}

// ---------------- router GEMM: 2-term fp16, CTA 256x64, warp 64x32, 3-stage ---
// stage bytes: A 256x40h = 20480, B0 32x72h = 4608, B1 4608  => 29696
#define GR_STG 29696

__global__ void __launch_bounds__(256) gemm_router2(float* __restrict__ C) {
    extern __shared__ __align__(16) char gsm[];
    const int tid  = threadIdx.x;
    const int warp = tid >> 5;
    const int wr   = warp >> 1;   // 0..3 -> 64 rows
    const int wc   = warp & 1;    // 0..1 -> 32 cols
    const int m0 = blockIdx.y * 256;
    const int n0 = blockIdx.x * 64;
    const uint32_t smb = smem_u32(gsm);

    wmma::fragment<wmma::accumulator, 16, 16, 16, float> acc[4][2];
    #pragma unroll
    for (int i = 0; i < 4; i++)
        #pragma unroll
        for (int j = 0; j < 2; j++) wmma::fill_fragment(acc[i][j], 0.0f);

    const __half* Ab = g_A1 + (size_t)m0 * KRR;

    auto load_stage = [&](int slot, int kt) {
        uint32_t ab = smb + slot * GR_STG;
        uint32_t b0b = ab + 20480;
        uint32_t b1b = b0b + 4608;
        #pragma unroll
        for (int q = 0; q < 4; q++) {
            int idx = tid + q * 256;
            int row = idx >> 2, c8 = (idx & 3) << 3;
            cp16(ab + row * 80 + c8 * 2, Ab + (size_t)row * KRR + kt + c8);
        }
        {
            int row = tid >> 3, c8 = (tid & 7) << 3;
            cp16(b0b + row * 144 + c8 * 2, g_B0 + (size_t)(kt + row) * HDIM + n0 + c8);
            cp16(b1b + row * 144 + c8 * 2, g_B1 + (size_t)(kt + row) * HDIM + n0 + c8);
        }
        CP_COMMIT();
    };

    load_stage(0, 0);
    load_stage(1, 32);
    load_stage(2, 64);

    const int nch = KRR / 32;   // 32
    for (int i = 0; i < nch; i++) {
        int rem = nch - 1 - i;
        CP_WAIT(rem);
        __syncthreads();
        int slot = i % 3;
        const __half* As  = reinterpret_cast<const __half*>(gsm + slot * GR_STG);
        const __half* B0s = reinterpret_cast<const __half*>(gsm + slot * GR_STG + 20480);
        const __half* B1s = reinterpret_cast<const __half*>(gsm + slot * GR_STG + 20480 + 4608);
        #pragma unroll
        for (int ks = 0; ks < 32; ks += 16) {
            wmma::fragment<wmma::matrix_a, 16, 16, 16, __half, wmma::row_major> af[4];
            wmma::fragment<wmma::matrix_b, 16, 16, 16, __half, wmma::row_major> b0[2], b1[2];
            #pragma unroll
            for (int ii = 0; ii < 4; ii++)
                wmma::load_matrix_sync(af[ii], As + (wr * 64 + ii * 16) * 40 + ks, 40);
            #pragma unroll
            for (int jj = 0; jj < 2; jj++) {
                wmma::load_matrix_sync(b0[jj], B0s + ks * 72 + wc * 32 + jj * 16, 72);
                wmma::load_matrix_sync(b1[jj], B1s + ks * 72 + wc * 32 + jj * 16, 72);
            }
            #pragma unroll
            for (int ii = 0; ii < 4; ii++)
                #pragma unroll
                for (int jj = 0; jj < 2; jj++) {
                    wmma::mma_sync(acc[ii][jj], af[ii], b0[jj], acc[ii][jj]);
                    wmma::mma_sync(acc[ii][jj], af[ii], b1[jj], acc[ii][jj]);
                }
        }
        __syncthreads();
        if (i + 3 < nch) load_stage(slot, (i + 3) * 32);
    }

    #pragma unroll
    for (int ii = 0; ii < 4; ii++)
        #pragma unroll
        for (int jj = 0; jj < 2; jj++) {
            float* Cp = C + (size_t)(m0 + wr * 64 + ii * 16) * HDIM + n0 + wc * 32 + jj * 16;
            wmma::store_matrix_sync(Cp, acc[ii][jj], HDIM, wmma::mem_row_major);
        }
}

// ---------------- bf16 GEMM: CTA 256x128, warp 64x64, 3-stage -----------------
// stage bytes: A 256x40 bf16 = 20480, B 32x136 bf16 = 8704 => 29184
#define GB_STG 29184

__global__ void __launch_bounds__(256) gemm_bf16(const bf16* __restrict__ A,
                                                 const bf16* __restrict__ B,
                                                 float* __restrict__ C,
                                                 int K, int NC) {
    extern __shared__ __align__(16) char gsm[];
    const int tid  = threadIdx.x;
    const int warp = tid >> 5;
    const int wr   = warp >> 1;   // 0..3 -> 64 rows
    const int wc   = warp & 1;    // 0..1 -> 64 cols
    const int m0 = blockIdx.y * 256;
    const int n0 = blockIdx.x * 128;
    const uint32_t smb = smem_u32(gsm);

    wmma::fragment<wmma::accumulator, 16, 16, 16, float> acc[4][4];
    #pragma unroll
    for (int i = 0; i < 4; i++)
        #pragma unroll
        for (int j = 0; j < 4; j++) wmma::fill_fragment(acc[i][j], 0.0f);

    auto load_stage = [&](int slot, int kt) {
        uint32_t ab = smb + slot * GB_STG;
        uint32_t bb = ab + 20480;
        #pragma unroll
        for (int q = 0; q < 4; q++) {
            int idx = tid + q * 256;
            int row = idx >> 2, c8 = (idx & 3) << 3;
            cp16(ab + row * 80 + c8 * 2, A + (size_t)(m0 + row) * K + kt + c8);
        }
        #pragma unroll
        for (int q = 0; q < 2; q++) {
            int idx = tid + q * 256;
            int row = idx >> 4, c8 = (idx & 15) << 3;
            cp16(bb + row * 272 + c8 * 2, B + (size_t)(kt + row) * NC + n0 + c8);
        }
        CP_COMMIT();
    };

    load_stage(0, 0);
    load_stage(1, 32);
    load_stage(2, 64);

    const int nch = K / 32;
    for (int i = 0; i < nch; i++) {
        int rem = nch - 1 - i;
        CP_WAIT(rem);
        __syncthreads();
        int slot = i % 3;
        const bf16* As = reinterpret_cast<const bf16*>(gsm + slot * GB_STG);
        const bf16* Bs = reinterpret_cast<const bf16*>(gsm + slot * GB_STG + 20480);
        #pragma unroll
        for (int ks = 0; ks < 32; ks += 16) {
            wmma::fragment<wmma::matrix_a, 16, 16, 16, bf16, wmma::row_major> af[4];
            wmma::fragment<wmma::matrix_b, 16, 16, 16, bf16, wmma::row_major> bfr[4];
            #pragma unroll
            for (int ii = 0; ii < 4; ii++)
                wmma::load_matrix_sync(af[ii], As + (wr * 64 + ii * 16) * 40 + ks, 40);
            #pragma unroll
            for (int jj = 0; jj < 4; jj++)
                wmma::load_matrix_sync(bfr[jj], Bs + ks * 136 + wc * 64 + jj * 16, 136);
            #pragma unroll
            for (int ii = 0; ii < 4; ii++)
                #pragma unroll
                for (int jj = 0; jj < 4; jj++)
                    wmma::mma_sync(acc[ii][jj], af[ii], bfr[jj], acc[ii][jj]);
        }
        __syncthreads();
        if (i + 3 < nch) load_stage(slot, (i + 3) * 32);
    }

    #pragma unroll
    for (int ii = 0; ii < 4; ii++)
        #pragma unroll
        for (int jj = 0; jj < 4; jj++) {
            float* Cp = C + (size_t)(m0 + wr * 64 + ii * 16) * NC + n0 + wc * 64 + jj * 16;
            wmma::store_matrix_sync(Cp, acc[ii][jj], NC, wmma::mem_row_major);
        }
}

// ---------------- router2: warp-per-row (unchanged from R12) ------------------
__global__ void __launch_bounds__(256) k_router2(
        const float* __restrict__ ep,
        const int* __restrict__ sid, const int* __restrict__ hc,
        const int* __restrict__ ps,
        const float* __restrict__ rb1, const float* __restrict__ rlg,
        const float* __restrict__ rlb,
        const float* __restrict__ b2, const float* __restrict__ proto,
        float* __restrict__ outC, float* __restrict__ outW) {
    const int warp = threadIdx.x >> 5, lane = threadIdx.x & 31;
    const int row = blockIdx.x * 8 + warp;
    int sI = min(max(sid[row], 0), 2048);
    int hI = min(max(hc[row], 0), 9);
    int pI = min(max(ps[row], 0), 7);
    const float4* h4p  = reinterpret_cast<const float4*>(&g_H1[(size_t)row * HDIM]);
    const float4* b4p  = reinterpret_cast<const float4*>(rb1);
    const float4* ts4p = reinterpret_cast<const float4*>(&g_TS[(size_t)sI * HDIM]);
    const float4* th4p = reinterpret_cast<const float4*>(&g_TH[(size_t)hI * HDIM]);
    const float4* tp4p = reinterpret_cast<const float4*>(&g_TP[(size_t)pI * HDIM]);
    float4 pre[4];
    float s1 = 0.0f, s2 = 0.0f;
    #pragma unroll
    for (int q = 0; q < 4; q++) {
        int c4 = lane + 32 * q;
        float4 h = h4p[c4], b = b4p[c4], ts = ts4p[c4], th = th4p[c4], tp = tp4p[c4];
        pre[q].x = h.x + b.x + ts.x + th.x + tp.x;
        pre[q].y = h.y + b.y + ts.y + th.y + tp.y;
        pre[q].z = h.z + b.z + ts.z + th.z + tp.z;
        pre[q].w = h.w + b.w + ts.w + th.w + tp.w;
        s1 += pre[q].x + pre[q].y + pre[q].z + pre[q].w;
        s2 += pre[q].x * pre[q].x + pre[q].y * pre[q].y
            + pre[q].z * pre[q].z + pre[q].w * pre[q].w;
    }
    s1 = warp_sum(s1);
    s2 = warp_sum(s2);
    float mean = s1 * (1.0f / 512.0f);
    float var  = s2 * (1.0f / 512.0f) - mean * mean;
    float rs = rsqrtf(var + 1e-5f);
    const float4* g4p  = reinterpret_cast<const float4*>(rlg);
    const float4* be4p = reinterpret_cast<const float4*>(rlb);
    float4 hv[4];
    #pragma unroll
    for (int q = 0; q < 4; q++) {
        int c4 = lane + 32 * q;
        float4 g = g4p[c4], be = be4p[c4];
        hv[q].x = gelu_exact((pre[q].x - mean) * rs * g.x + be.x);
        hv[q].y = gelu_exact((pre[q].y - mean) * rs * g.y + be.y);
        hv[q].z = gelu_exact((pre[q].z - mean) * rs * g.z + be.z);
        hv[q].w = gelu_exact((pre[q].w - mean) * rs * g.w + be.w);
    }
    float lg[PROTO];
    #pragma unroll
    for (int l = 0; l < PROTO; l++) {
        const float4* wl = reinterpret_cast<const float4*>(&g_W2T[l * HDIM]);
        float sa = 0.0f;
        #pragma unroll
        for (int q = 0; q < 4; q++) {
            float4 w = wl[lane + 32 * q];
            sa = fmaf(hv[q].x, w.x, sa);
            sa = fmaf(hv[q].y, w.y, sa);
            sa = fmaf(hv[q].z, w.z, sa);
            sa = fmaf(hv[q].w, w.w, sa);
        }
        lg[l] = warp_sum(sa);
    }
    float sw[PROTO];
    if (lane == 0) {
        float w[PROTO];
        #pragma unroll
        for (int i = 0; i < PROTO; i++) w[i] = lg[i] + b2[i];
        float v[PROTO];
        #pragma unroll
        for (int i = 0; i < PROTO; i++) v[i] = w[i];
        float top5[5];
        #pragma unroll
        for (int k = 0; k < 5; k++) {
            int bi = 0; float bv = -1e30f;
            #pragma unroll
            for (int i = 0; i < PROTO; i++)
                if (v[i] > bv) { bv = v[i]; bi = i; }
            top5[k] = bv; v[bi] = -1e30f;
        }
        if (top5[3] - top5[4] < 2e-3f) {
            int pos = atomicAdd(&g_count, 1);
            g_LIST[pos] = row;
        }
        float mx = top5[0];
        float ssum = 0.0f;
        #pragma unroll
        for (int i = 0; i < PROTO; i++) { w[i] = expf(w[i] - mx); ssum += w[i]; }
        float inv = 1.0f / ssum;
        #pragma unroll
        for (int i = 0; i < PROTO; i++) w[i] *= inv;
        bool sel[PROTO];
        #pragma unroll
        for (int i = 0; i < PROTO; i++) sel[i] = false;
        for (int k = 0; k < 4; k++) {
            int bi = -1; float bv = -1e30f;
            #pragma unroll
            for (int i = 0; i < PROTO; i++)
                if (!sel[i] && w[i] > bv) { bv = w[i]; bi = i; }
            sel[bi] = true;
        }
        float s22 = 0.0f;
        #pragma unroll
        for (int i = 0; i < PROTO; i++) { float vv = sel[i] ? w[i] : 0.0f; sw[i] = vv; s22 += vv; }
        float d = 1.0f / fmaxf(s22, 1e-6f);
        #pragma unroll
        for (int i = 0; i < PROTO; i++) sw[i] *= d;
    }
    #pragma unroll
    for (int i = 0; i < PROTO; i++) sw[i] = __shfl_sync(0xffffffffu, sw[i], 0);
    if (lane == 0) {
        float* ow = &outW[(size_t)row * PROTO];
        #pragma unroll
        for (int i = 0; i < PROTO; i++) ow[i] = sw[i];
    }
    const float4* e4p = reinterpret_cast<const float4*>(&ep[(size_t)row * HDIM]);
    float4* oc4p = reinterpret_cast<float4*>(&outC[(size_t)row * HDIM]);
    bf16* frow = &g_FEATSH[(size_t)row * KFN];
    #pragma unroll
    for (int q = 0; q < 4; q++) {
        int c4 = lane + 32 * q;
        float4 c = make_float4(0.f, 0.f, 0.f, 0.f);
        #pragma unroll
        for (int p = 0; p < PROTO; p++) {
            float wv = sw[p];
            float4 pv = reinterpret_cast<const float4*>(&proto[p * HDIM])[c4];
            c.x = fmaf(wv, pv.x, c.x);
            c.y = fmaf(wv, pv.y, c.y);
            c.z = fmaf(wv, pv.z, c.z);
            c.w = fmaf(wv, pv.w, c.w);
        }
        float4 e = e4p[c4];
        oc4p[c4] = c;
        st_bf4(frow + 4 * c4, e);
        st_bf4(frow + 512 + 4 * c4, make_float4(fabsf(e.x - c.x), fabsf(e.y - c.y),
                                                fabsf(e.z - c.z), fabsf(e.w - c.w)));
        st_bf4(frow + 1024 + 4 * c4, make_float4(e.x * c.x, e.y * c.y,
                                                 e.z * c.z, e.w * c.w));
    }
    if (lane < 16) {
        float a = (lane * 2 < PROTO)     ? sw[lane * 2]     : 0.0f;
        float b = (lane * 2 + 1 < PROTO) ? sw[lane * 2 + 1] : 0.0f;
        reinterpret_cast<unsigned*>(frow + 1536)[lane] = pack_bf2(a, b);
    }
}

// ---------------- rescue (exact fp32 path, unchanged) -------------------------
__global__ void __launch_bounds__(128) k_rescue(
        const float* __restrict__ pair, const float* __restrict__ ep,
        const int* __restrict__ sid, const int* __restrict__ hc, const int* __restrict__ ps,
        const float* __restrict__ se, const float* __restrict__ he, const float* __restrict__ soe,
        const float* __restrict__ rw1, const float* __restrict__ rb1,
        const float* __restrict__ rlg, const float* __restrict__ rlb,
        const float* __restrict__ b2, const float* __restrict__ proto,
        float* __restrict__ outC, float* __restrict__ outW) {
    __shared__ float sa[KR];
    __shared__ float shd[HDIM];
    __shared__ double dbuf[4];
    __shared__ float sl[PROTO];
    __shared__ float sw[PROTO];
    int t = threadIdx.x, warp = t >> 5, lane = t & 31;
    int cnt = g_count;
    for (int li = blockIdx.x; li < cnt; li += gridDim.x) {
        int row = g_LIST[li];
        int s = min(max(sid[row], 0), 2048);
        int h = min(max(hc[row], 0), 9);
        int p = min(max(ps[row], 0), 7);
        const float* pr = &pair[(size_t)row * HDIM];
        const float* er = &ep[(size_t)row * HDIM];
        for (int k = t; k < KR; k += 128) {
            float v;
            if      (k < 512)  v = pr[k];
            else if (k < 1024) v = er[k - 512];
            else if (k < 1152) v = se[s * MD + (k - 1024)];
            else if (k < 1280) v = he[h * MD + (k - 1152)];
            else               v = soe[p * MD + (k - 1280)];
            sa[k] = v;
        }
        __syncthreads();
        float hs[4], hcmp[4];
        #pragma unroll
        for (int j = 0; j < 4; j++) { hs[j] = 0.0f; hcmp[j] = 0.0f; }
        for (int k = 0; k < KR; k++) {
            float a = sa[k];
            const float* wr = &rw1[(size_t)k * HDIM];
            #pragma unroll
            for (int j = 0; j < 4; j++) {
                int c = t + j * 128;
                float w = wr[c];
                float pp = a * w;
                float pe = fmaf(a, w, -pp);
                twosum_acc(hs[j], hcmp[j], pp);
                hcmp[j] += pe;
            }
        }
        float pre[4];
        double msum = 0.0;
        #pragma unroll
        for (int j = 0; j < 4; j++) {
            pre[j] = (hs[j] + hcmp[j]) + rb1[t + j * 128];
            msum += (double)pre[j];
        }
        double mean = block_sum_128d(msum, dbuf) * (1.0 / 512.0);
        double vsum = 0.0;
        #pragma unroll
        for (int j = 0; j < 4; j++) {
            double e0 = (double)pre[j] - mean;
            vsum += e0 * e0;
        }
        double var = block_sum_128d(vsum, dbuf) * (1.0 / 512.0);
        float rs = (float)(1.0 / sqrt(var + 1e-5));
        #pragma unroll
        for (int j = 0; j < 4; j++) {
            int c = t + j * 128;
            shd[c] = gelu_exact((float)((double)pre[j] - mean) * rs * rlg[c] + rlb[c]);
        }
        __syncthreads();
        for (int l = warp; l < PROTO; l += 4) {
            float ss = 0.0f, cmp = 0.0f;
            const float* wl = &g_W2T[l * HDIM];
            for (int c = lane; c < HDIM; c += 32) {
                float a = shd[c], w = wl[c];
                float pp = a * w;
                float pe = fmaf(a, w, -pp);
                twosum_acc(ss, cmp, pp);
                cmp += pe;
            }
            #pragma unroll
            for (int o = 16; o; o >>= 1) {
                ss  += __shfl_xor_sync(0xffffffffu, ss, o);
                cmp += __shfl_xor_sync(0xffffffffu, cmp, o);
            }
            if (lane == 0) sl[l] = (ss + cmp) + b2[l];
        }
        __syncthreads();
        if (t == 0) {
            float w[PROTO];
            float mx = -1e30f;
            #pragma unroll
            for (int i = 0; i < PROTO; i++) mx = fmaxf(mx, sl[i]);
            float ssum = 0.0f;
            #pragma unroll
            for (int i = 0; i < PROTO; i++) { w[i] = expf(sl[i] - mx); ssum += w[i]; }
            float inv = 1.0f / ssum;
            #pragma unroll
            for (int i = 0; i < PROTO; i++) w[i] *= inv;
            bool sel[PROTO];
            #pragma unroll
            for (int i = 0; i < PROTO; i++) sel[i] = false;
            for (int k = 0; k < 4; k++) {
                int bi = -1; float bv = -1e30f;
                #pragma unroll
                for (int i = 0; i < PROTO; i++)
                    if (!sel[i] && w[i] > bv) { bv = w[i]; bi = i; }
                sel[bi] = true;
            }
            float s2 = 0.0f;
            #pragma unroll
            for (int i = 0; i < PROTO; i++) { float vv = sel[i] ? w[i] : 0.0f; sw[i] = vv; s2 += vv; }
            float d = 1.0f / fmaxf(s2, 1e-6f);
            #pragma unroll
            for (int i = 0; i < PROTO; i++) sw[i] *= d;
        }
        __syncthreads();
        if (t < PROTO) outW[(size_t)row * PROTO + t] = sw[t];
        bf16* frow = &g_FEATSH[(size_t)row * KFN];
        for (int j = t; j < HDIM; j += 128) {
            float c = 0.0f;
            #pragma unroll
            for (int pp = 0; pp < PROTO; pp++) c += sw[pp] * proto[pp * HDIM + j];
            float e = er[j];
            outC[(size_t)row * HDIM + j] = c;
            frow[j]        = __float2bfloat16_rn(e);
            frow[512 + j]  = __float2bfloat16_rn(fabsf(e - c));
            frow[1024 + j] = __float2bfloat16_rn(e * c);
        }
        if (t < 32) frow[1536 + t] = __float2bfloat16_rn(t < PROTO ? sw[t] : 0.0f);
        __syncthreads();
    }
}

// ---------------- activations: warp-per-row (unchanged) -----------------------
__global__ void __launch_bounds__(256) k_act(
        const float* __restrict__ b_mu, const float* __restrict__ g_mu,
        const float* __restrict__ be_mu, const float* __restrict__ b_mg) {
    const int warp = threadIdx.x >> 5, lane = threadIdx.x & 31;
    const int row = blockIdx.x * 8 + warp;
    const float4* h12 = reinterpret_cast<const float4*>(&g_H12[(size_t)row * 1024]);
    const float4* bm4 = reinterpret_cast<const float4*>(b_mu);
    float4 m[4];
    float s1 = 0.0f, s2 = 0.0f;
    #pragma unroll
    for (int q = 0; q < 4; q++) {
        int c4 = lane + 32 * q;
        float4 h = h12[c4], b = bm4[c4];
        m[q].x = h.x + b.x; m[q].y = h.y + b.y;
        m[q].z = h.z + b.z; m[q].w = h.w + b.w;
        s1 += m[q].x + m[q].y + m[q].z + m[q].w;
        s2 += m[q].x * m[q].x + m[q].y * m[q].y + m[q].z * m[q].z + m[q].w * m[q].w;
    }
    s1 = warp_sum(s1);
    s2 = warp_sum(s2);
    float mean = s1 * (1.0f / 512.0f);
    float var  = s2 * (1.0f / 512.0f) - mean * mean;
    float rs = rsqrtf(var + 1e-5f);
    const float4* g4p  = reinterpret_cast<const float4*>(g_mu);
    const float4* be4p = reinterpret_cast<const float4*>(be_mu);
    const float4* bg4p = reinterpret_cast<const float4*>(b_mg);
    bf16* xm = &g_HMUH[(size_t)row * HDIM];
    bf16* xg = &g_HMGH[(size_t)row * HDIM];
    #pragma unroll
    for (int q = 0; q < 4; q++) {
        int c4 = lane + 32 * q;
        float4 g = g4p[c4], be = be4p[c4];
        float4 o;
        o.x = gelu_exact((m[q].x - mean) * rs * g.x + be.x);
        o.y = gelu_exact((m[q].y - mean) * rs * g.y + be.y);
        o.z = gelu_exact((m[q].z - mean) * rs * g.z + be.z);
        o.w = gelu_exact((m[q].w - mean) * rs * g.w + be.w);
        st_bf4(xm + 4 * c4, o);
        float4 gg = h12[128 + c4], bg = bg4p[c4];
        float4 og;
        og.x = gelu_exact(gg.x + bg.x);
        og.y = gelu_exact(gg.y + bg.y);
        og.z = gelu_exact(gg.z + bg.z);
        og.w = gelu_exact(gg.w + bg.w);
        st_bf4(xg + 4 * c4, og);
    }
}

// ---------------- final: warp-per-row (unchanged) -----------------------------
__global__ void __launch_bounds__(256) k_final(
        const float* __restrict__ ep, const float* __restrict__ mub2,
        const float* __restrict__ mgb2, const float* __restrict__ ng,
        const float* __restrict__ nb, float* __restrict__ outU) {
    const int warp = threadIdx.x >> 5, lane = threadIdx.x & 31;
    const int row = blockIdx.x * 8 + warp;
    const float4* e4p  = reinterpret_cast<const float4*>(&ep[(size_t)row * HDIM]);
    const float4* d4p  = reinterpret_cast<const float4*>(&g_DELTA[(size_t)row * HDIM]);
    const float4* gp4p = reinterpret_cast<const float4*>(&g_GATE[(size_t)row * HDIM]);
    const float4* db4p = reinterpret_cast<const float4*>(mub2);
    const float4* gb4p = reinterpret_cast<const float4*>(mgb2);
    float4 u[4];
    float s1 = 0.0f, s2 = 0.0f;
    #pragma unroll
    for (int q = 0; q < 4; q++) {
        int c4 = lane + 32 * q;
        float4 e = e4p[c4], d = d4p[c4], gp = gp4p[c4], db = db4p[c4], gb = gb4p[c4];
        u[q].x = e.x + RSCALE * (1.0f / (1.0f + expf(-(gp.x + gb.x)))) * (d.x + db.x);
        u[q].y = e.y + RSCALE * (1.0f / (1.0f + expf(-(gp.y + gb.y)))) * (d.y + db.y);
        u[q].z = e.z + RSCALE * (1.0f / (1.0f + expf(-(gp.z + gb.z)))) * (d.z + db.z);
        u[q].w = e.w + RSCALE * (1.0f / (1.0f + expf(-(gp.w + gb.w)))) * (d.w + db.w);
        s1 += u[q].x + u[q].y + u[q].z + u[q].w;
        s2 += u[q].x * u[q].x + u[q].y * u[q].y + u[q].z * u[q].z + u[q].w * u[q].w;
    }
    s1 = warp_sum(s1);
    s2 = warp_sum(s2);
    float mean = s1 * (1.0f / 512.0f);
    float var  = s2 * (1.0f / 512.0f) - mean * mean;
    float rs = rsqrtf(var + 1e-5f);
    const float4* g4p = reinterpret_cast<const float4*>(ng);
    const float4* b4p = reinterpret_cast<const float4*>(nb);
    float4* ou = reinterpret_cast<float4*>(&outU[(size_t)row * HDIM]);
    #pragma unroll
    for (int q = 0; q < 4; q++) {
        int c4 = lane + 32 * q;
        float4 g = g4p[c4], b = b4p[c4];
        float4 o;
        o.x = (u[q].x - mean) * rs * g.x + b.x;
        o.y = (u[q].y - mean) * rs * g.y + b.y;
        o.z = (u[q].z - mean) * rs * g.z + b.z;
        o.w = (u[q].w - mean) * rs * g.w + b.w;
        ou[c4] = o;
    }
}

// ---------------- launch ----------------
extern "C" void kernel_launch(void* const* d_in, const int* in_sizes, int n_in,
                              void* d_out, int out_size) {
    const float* pair = (const float*)d_in[0];
    const float* ep   = (const float*)d_in[1];
    const int*   sid  = (const int*)d_in[2];
    const int*   hc   = (const int*)d_in[3];
    const int*   ps   = (const int*)d_in[4];
    const float* se   = (const float*)d_in[5];
    const float* he   = (const float*)d_in[6];
    const float* soe  = (const float*)d_in[7];
    const float* proto= (const float*)d_in[8];
    const float* rw1  = (const float*)d_in[9];
    const float* rb1  = (const float*)d_in[10];
    const float* rlg  = (const float*)d_in[11];
    const float* rlb  = (const float*)d_in[12];
    const float* rw2  = (const float*)d_in[13];
    const float* rb2  = (const float*)d_in[14];
    const float* muw1 = (const float*)d_in[15];
    const float* mub1 = (const float*)d_in[16];
    const float* mulg = (const float*)d_in[17];
    const float* mulb = (const float*)d_in[18];
    const float* muw2 = (const float*)d_in[19];
    const float* mub2 = (const float*)d_in[20];
    const float* mgw1 = (const float*)d_in[21];
    const float* mgb1 = (const float*)d_in[22];
    const float* mgw2 = (const float*)d_in[23];
    const float* mgb2 = (const float*)d_in[24];
    const float* ng   = (const float*)d_in[25];
    const float* nb   = (const float*)d_in[26];

    float* outU = (float*)d_out;
    float* outC = outU + (size_t)NROWS * HDIM;
    float* outW = outC + (size_t)NROWS * HDIM;

    float *pH1, *pH12, *pDELTA, *pGATE;
    bf16 *pFEATSH, *pHMUH, *pHMGH, *pW1, *pW2MU, *pW2MG;
    cudaGetSymbolAddress((void**)&pH1,     g_H1);
    cudaGetSymbolAddress((void**)&pH12,    g_H12);
    cudaGetSymbolAddress((void**)&pDELTA,  g_DELTA);
    cudaGetSymbolAddress((void**)&pGATE,   g_GATE);
    cudaGetSymbolAddress((void**)&pFEATSH, g_FEATSH);
    cudaGetSymbolAddress((void**)&pHMUH,   g_HMUH);
    cudaGetSymbolAddress((void**)&pHMGH,   g_HMGH);
    cudaGetSymbolAddress((void**)&pW1,     g_W1);
    cudaGetSymbolAddress((void**)&pW2MU,   g_W2MU);
    cudaGetSymbolAddress((void**)&pW2MG,   g_W2MG);

    static bool attr_set = false;
    if (!attr_set) {
        cudaFuncSetAttribute(gemm_router2, cudaFuncAttributeMaxDynamicSharedMemorySize,
                             3 * GR_STG);
        cudaFuncSetAttribute(gemm_bf16, cudaFuncAttributeMaxDynamicSharedMemorySize,
                             3 * GB_STG);
        attr_set = true;
    }

    k_prep<<<4096, 256>>>(rw1, rw2, muw1, mgw1, muw2, mgw2, se, he, soe, proto);
    k_gather<<<NROWS, 128>>>(pair, ep);
    {
        dim3 grid(HDIM / 64, NROWS / 256);     // (8, 256)
        gemm_router2<<<grid, 256, 3 * GR_STG>>>(pH1);
    }
    k_router2<<<NROWS / 8, 256>>>(ep, sid, hc, ps, rb1, rlg, rlb, rb2, proto, outC, outW);
    k_rescue<<<2048, 128>>>(pair, ep, sid, hc, ps, se, he, soe,
                            rw1, rb1, rlg, rlb, rb2, proto, outC, outW);
    {
        dim3 grid(1024 / 128, NROWS / 256);    // (8, 256)
        gemm_bf16<<<grid, 256, 3 * GB_STG>>>(pFEATSH, pW1, pH12, KFN, 1024);
    }
    k_act<<<NROWS / 8, 256>>>(mub1, mulg, mulb, mgb1);
    {
        dim3 grid(HDIM / 128, NROWS / 256);    // (4, 256)
        gemm_bf16<<<grid, 256, 3 * GB_STG>>>(pHMUH, pW2MU, pDELTA, HDIM, HDIM);
        gemm_bf16<<<grid, 256, 3 * GB_STG>>>(pHMGH, pW2MG, pGATE, HDIM, HDIM);
    }
    k_final<<<NROWS / 8, 256>>>(ep, mub2, mgb2, ng, nb, outU);
}

// round 15
// speedup vs baseline: 1.0527x; 1.0004x over previous
#include <cuda_runtime.h>
#include <cuda_bf16.h>
#include <cuda_fp16.h>
#include <mma.h>
#include <math.h>
#include <stdint.h>

using namespace nvcuda;

#define NROWS 65536
#define HDIM  512
#define MD    128
#define PROTO 12
#define KR    1408
#define KRR   1024
#define KFN   1568
#define RSCALE 0.2f

typedef __nv_bfloat16 bf16;

// ---------------- scratch (device globals; allocation-free) ----------------
__device__ __align__(1024) __half g_A1 [(size_t)NROWS * KRR];
__device__ __align__(1024) __half g_B0 [(size_t)KRR * HDIM];
__device__ __align__(1024) __half g_B1 [(size_t)KRR * HDIM];
__device__ __align__(16)   float g_TS  [(size_t)2049 * HDIM];
__device__ __align__(16)   float g_TH  [(size_t)10 * HDIM];
__device__ __align__(16)   float g_TP  [(size_t)8 * HDIM];
__device__ __align__(16)   float g_H1  [(size_t)NROWS * HDIM];
__device__ __align__(1024) bf16  g_FEATSH[(size_t)NROWS * KFN];
__device__ __align__(1024) bf16  g_H12H[(size_t)NROWS * 1024];
__device__ __align__(1024) bf16  g_HMUH[(size_t)NROWS * HDIM];
__device__ __align__(1024) bf16  g_HMGH[(size_t)NROWS * HDIM];
__device__ __align__(1024) bf16  g_DELTAH[(size_t)NROWS * HDIM];
__device__ __align__(1024) bf16  g_GATEH [(size_t)NROWS * HDIM];
__device__ __align__(1024) bf16  g_W1  [(size_t)KFN * 1024];
__device__ __align__(1024) bf16  g_W2MU[(size_t)HDIM * HDIM];
__device__ __align__(1024) bf16  g_W2MG[(size_t)HDIM * HDIM];
__device__ __align__(16)   float g_W2T [(size_t)PROTO * HDIM];
__device__ int g_count;
__device__ int g_LIST[NROWS];

// ---------------- helpers ----------------
__device__ __forceinline__ float gelu_exact(float x) {
    return 0.5f * x * (1.0f + erff(x * 0.70710678118654752440f));
}
__device__ __forceinline__ float warp_sum(float v) {
    #pragma unroll
    for (int o = 16; o; o >>= 1) v += __shfl_xor_sync(0xffffffffu, v, o);
    return v;
}
__device__ __forceinline__ double block_sum_128d(double v, double* sbuf) {
    #pragma unroll
    for (int o = 16; o; o >>= 1) v += __shfl_xor_sync(0xffffffffu, v, o);
    int w = threadIdx.x >> 5;
    if ((threadIdx.x & 31) == 0) sbuf[w] = v;
    __syncthreads();
    double r = sbuf[0] + sbuf[1] + sbuf[2] + sbuf[3];
    __syncthreads();
    return r;
}
__device__ __forceinline__ void twosum_acc(float& sum, float& comp, float v) {
    float s = sum + v;
    float z = s - sum;
    float e = (sum - (s - z)) + (v - z);
    sum = s;
    comp += e;
}
__device__ __forceinline__ void cp16(uint32_t dst, const void* src) {
    asm volatile("cp.async.cg.shared.global [%0], [%1], 16;" :: "r"(dst), "l"(src) : "memory");
}
__device__ __forceinline__ uint32_t smem_u32(const void* p) {
    uint32_t a;
    asm("{ .reg .u64 t; cvta.to.shared.u64 t, %1; cvt.u32.u64 %0, t; }" : "=r"(a) : "l"(p));
    return a;
}
#define CP_COMMIT() asm volatile("cp.async.commit_group;" ::: "memory")
#define CP_WAIT(rem) do { \
    if ((rem) >= 2)      asm volatile("cp.async.wait_group 2;" ::: "memory"); \
    else if ((rem) == 1) asm volatile("cp.async.wait_group 1;" ::: "memory"); \
    else                 asm volatile("cp.async.wait_group 0;" ::: "memory"); \
} while (0)

__device__ __forceinline__ unsigned pack_bf2(float a, float b) {
    return ((unsigned)__bfloat16_as_ushort(__float2bfloat16_rn(b)) << 16)
         |  (unsigned)__bfloat16_as_ushort(__float2bfloat16_rn(a));
}
__device__ __forceinline__ void st_bf4(bf16* p, float4 v) {
    uint2 u;
    u.x = pack_bf2(v.x, v.y);
    u.y = pack_bf2(v.z, v.w);
    *reinterpret_cast<uint2*>(p) = u;
}
__device__ __forceinline__ float4 ld_bf4(const bf16* p) {
    uint2 u = *reinterpret_cast<const uint2*>(p);
    __nv_bfloat162 a = *reinterpret_cast<__nv_bfloat162*>(&u.x);
    __nv_bfloat162 b = *reinterpret_cast<__nv_bfloat162*>(&u.y);
    return make_float4(__bfloat162float(a.x), __bfloat162float(a.y),
                       __bfloat162float(b.x), __bfloat162float(b.y));
}

// ---------------- k_prep (unchanged) ------------------------------------------
__global__ void k_prep(const float* __restrict__ rw1, const float* __restrict__ rw2,
                       const float* __restrict__ muw1, const float* __restrict__ mgw1,
                       const float* __restrict__ muw2, const float* __restrict__ mgw2,
                       const float* __restrict__ se, const float* __restrict__ he,
                       const float* __restrict__ soe, const float* __restrict__ proto) {
    int gtid = blockIdx.x * blockDim.x + threadIdx.x;
    int gs = blockDim.x * gridDim.x;
    if (gtid == 0) g_count = 0;
    for (int i = gtid; i < KRR * HDIM; i += gs) {
        float v = rw1[i];
        __half h0 = __float2half_rn(v);
        __half h1 = __float2half_rn(v - __half2float(h0));
        g_B0[i] = h0; g_B1[i] = h1;
    }
    for (int i = gtid; i < 2049 * HDIM; i += gs) {
        int b = i >> 9, c = i & 511;
        float acc = 0.0f;
        for (int j = 0; j < MD; j++)
            acc = fmaf(se[b * MD + j], rw1[(size_t)(1024 + j) * HDIM + c], acc);
        g_TS[i] = acc;
    }
    for (int i = gtid; i < 10 * HDIM; i += gs) {
        int b = i >> 9, c = i & 511;
        float acc = 0.0f;
        for (int j = 0; j < MD; j++)
            acc = fmaf(he[b * MD + j], rw1[(size_t)(1152 + j) * HDIM + c], acc);
        g_TH[i] = acc;
    }
    for (int i = gtid; i < 8 * HDIM; i += gs) {
        int b = i >> 9, c = i & 511;
        float acc = 0.0f;
        for (int j = 0; j < MD; j++)
            acc = fmaf(soe[b * MD + j], rw1[(size_t)(1280 + j) * HDIM + c], acc);
        g_TP[i] = acc;
    }
    for (int i = gtid; i < 1536 * HDIM; i += gs) {
        int k = i >> 9, c = i & 511;
        int ok = (k < 512) ? k : k + 512;
        g_W1[(size_t)k * 1024 + c]       = __float2bfloat16_rn(muw1[(size_t)ok * HDIM + c]);
        g_W1[(size_t)k * 1024 + 512 + c] = __float2bfloat16_rn(mgw1[(size_t)ok * HDIM + c]);
    }
    for (int i = gtid; i < 32 * 1024; i += gs) {
        int kk = i >> 10, c = i & 1023;
        float acc = 0.0f;
        if (kk < PROTO) {
            if (c < 512) {
                for (int j = 0; j < 512; j++)
                    acc = fmaf(proto[kk * HDIM + j], muw1[(size_t)(512 + j) * HDIM + c], acc);
            } else {
                for (int j = 0; j < 512; j++)
                    acc = fmaf(proto[kk * HDIM + j], mgw1[(size_t)(512 + j) * HDIM + (c - 512)], acc);
            }
        }
        g_W1[(size_t)(1536 + kk) * 1024 + c] = __float2bfloat16_rn(acc);
    }
    for (int i = gtid; i < HDIM * HDIM; i += gs) {
        g_W2MU[i] = __float2bfloat16_rn(muw2[i]);
        g_W2MG[i] = __float2bfloat16_rn(mgw2[i]);
    }
    for (int i = gtid; i < PROTO * HDIM; i += gs) {
        int l = i / HDIM, c = i - l * HDIM;
        g_W2T[i] = rw2[(size_t)c * PROTO + l];
    }
}

// ---------------- gather -> fp16 (unchanged) ----------------------------------
__global__ void k_gather(const float* __restrict__ pair, const float* __restrict__ ep) {
    int row = blockIdx.x;
    const float4* pr = reinterpret_cast<const float4*>(&pair[(size_t)row * HDIM]);
    const float4* er = reinterpret_cast<const float4*>(&ep[(size_t)row * HDIM]);
    __half* dst = &g_A1[(size_t)row * KRR];
    for (int v = threadIdx.x; v < KRR / 4; v += blockDim.x) {
        float4 f = (v < 128) ? pr[v] : er[v - 128];
        uint2 u;
        u.x = ((unsigned)__half_as_ushort(__float2half_rn(f.y)) << 16)
            |  (unsigned)__half_as_ushort(__float2half_rn(f.x));
        u.y = ((unsigned)__half_as_ushort(__float2half_rn(f.w)) << 16)
            |  (unsigned)__half_as_ushort(__float2half_rn(f.z));
        *reinterpret_cast<uint2*>(dst + 4 * v) = u;
    }
}

// ---------------- router GEMM (unchanged, fp32 out) ---------------------------
#define GR_STG 29696

__global__ void __launch_bounds__(256) gemm_router2(float* __restrict__ C) {
    extern __shared__ __align__(16) char gsm[];
    const int tid  = threadIdx.x;
    const int warp = tid >> 5;
    const int wr   = warp >> 1;
    const int wc   = warp & 1;
    const int m0 = blockIdx.y * 256;
    const int n0 = blockIdx.x * 64;
    const uint32_t smb = smem_u32(gsm);

    wmma::fragment<wmma::accumulator, 16, 16, 16, float> acc[4][2];
    #pragma unroll
    for (int i = 0; i < 4; i++)
        #pragma unroll
        for (int j = 0; j < 2; j++) wmma::fill_fragment(acc[i][j], 0.0f);

    const __half* Ab = g_A1 + (size_t)m0 * KRR;

    auto load_stage = [&](int slot, int kt) {
        uint32_t ab = smb + slot * GR_STG;
        uint32_t b0b = ab + 20480;
        uint32_t b1b = b0b + 4608;
        #pragma unroll
        for (int q = 0; q < 4; q++) {
            int idx = tid + q * 256;
            int row = idx >> 2, c8 = (idx & 3) << 3;
            cp16(ab + row * 80 + c8 * 2, Ab + (size_t)row * KRR + kt + c8);
        }
        {
            int row = tid >> 3, c8 = (tid & 7) << 3;
            cp16(b0b + row * 144 + c8 * 2, g_B0 + (size_t)(kt + row) * HDIM + n0 + c8);
            cp16(b1b + row * 144 + c8 * 2, g_B1 + (size_t)(kt + row) * HDIM + n0 + c8);
        }
        CP_COMMIT();
    };

    load_stage(0, 0);
    load_stage(1, 32);
    load_stage(2, 64);

    const int nch = KRR / 32;
    for (int i = 0; i < nch; i++) {
        int rem = nch - 1 - i;
        CP_WAIT(rem);
        __syncthreads();
        int slot = i % 3;
        const __half* As  = reinterpret_cast<const __half*>(gsm + slot * GR_STG);
        const __half* B0s = reinterpret_cast<const __half*>(gsm + slot * GR_STG + 20480);
        const __half* B1s = reinterpret_cast<const __half*>(gsm + slot * GR_STG + 20480 + 4608);
        #pragma unroll
        for (int ks = 0; ks < 32; ks += 16) {
            wmma::fragment<wmma::matrix_a, 16, 16, 16, __half, wmma::row_major> af[4];
            wmma::fragment<wmma::matrix_b, 16, 16, 16, __half, wmma::row_major> b0[2], b1[2];
            #pragma unroll
            for (int ii = 0; ii < 4; ii++)
                wmma::load_matrix_sync(af[ii], As + (wr * 64 + ii * 16) * 40 + ks, 40);
            #pragma unroll
            for (int jj = 0; jj < 2; jj++) {
                wmma::load_matrix_sync(b0[jj], B0s + ks * 72 + wc * 32 + jj * 16, 72);
                wmma::load_matrix_sync(b1[jj], B1s + ks * 72 + wc * 32 + jj * 16, 72);
            }
            #pragma unroll
            for (int ii = 0; ii < 4; ii++)
                #pragma unroll
                for (int jj = 0; jj < 2; jj++) {
                    wmma::mma_sync(acc[ii][jj], af[ii], b0[jj], acc[ii][jj]);
                    wmma::mma_sync(acc[ii][jj], af[ii], b1[jj], acc[ii][jj]);
                }
        }
        __syncthreads();
        if (i + 3 < nch) load_stage(slot, (i + 3) * 32);
    }

    #pragma unroll
    for (int ii = 0; ii < 4; ii++)
        #pragma unroll
        for (int jj = 0; jj < 2; jj++) {
            float* Cp = C + (size_t)(m0 + wr * 64 + ii * 16) * HDIM + n0 + wc * 32 + jj * 16;
            wmma::store_matrix_sync(Cp, acc[ii][jj], HDIM, wmma::mem_row_major);
        }
}

// ---------------- bf16 GEMM, bf16 OUTPUT epilogue (FIXED ldm=20) --------------
#define GB_STG 29184

__global__ void __launch_bounds__(256) gemm_bf16o(const bf16* __restrict__ A,
                                                  const bf16* __restrict__ B,
                                                  bf16* __restrict__ C,
                                                  int K, int NC) {
    extern __shared__ __align__(16) char gsm[];
    const int tid  = threadIdx.x;
    const int warp = tid >> 5;
    const int lane = tid & 31;
    const int wr   = warp >> 1;
    const int wc   = warp & 1;
    const int m0 = blockIdx.y * 256;
    const int n0 = blockIdx.x * 128;
    const uint32_t smb = smem_u32(gsm);

    wmma::fragment<wmma::accumulator, 16, 16, 16, float> acc[4][4];
    #pragma unroll
    for (int i = 0; i < 4; i++)
        #pragma unroll
        for (int j = 0; j < 4; j++) wmma::fill_fragment(acc[i][j], 0.0f);

    auto load_stage = [&](int slot, int kt) {
        uint32_t ab = smb + slot * GB_STG;
        uint32_t bb = ab + 20480;
        #pragma unroll
        for (int q = 0; q < 4; q++) {
            int idx = tid + q * 256;
            int row = idx >> 2, c8 = (idx & 3) << 3;
            cp16(ab + row * 80 + c8 * 2, A + (size_t)(m0 + row) * K + kt + c8);
        }
        #pragma unroll
        for (int q = 0; q < 2; q++) {
            int idx = tid + q * 256;
            int row = idx >> 4, c8 = (idx & 15) << 3;
            cp16(bb + row * 272 + c8 * 2, B + (size_t)(kt + row) * NC + n0 + c8);
        }
        CP_COMMIT();
    };

    load_stage(0, 0);
    load_stage(1, 32);
    load_stage(2, 64);

    const int nch = K / 32;
    for (int i = 0; i < nch; i++) {
        int rem = nch - 1 - i;
        CP_WAIT(rem);
        __syncthreads();
        int slot = i % 3;
        const bf16* As = reinterpret_cast<const bf16*>(gsm + slot * GB_STG);
        const bf16* Bs = reinterpret_cast<const bf16*>(gsm + slot * GB_STG + 20480);
        #pragma unroll
        for (int ks = 0; ks < 32; ks += 16) {
            wmma::fragment<wmma::matrix_a, 16, 16, 16, bf16, wmma::row_major> af[4];
            wmma::fragment<wmma::matrix_b, 16, 16, 16, bf16, wmma::row_major> bfr[4];
            #pragma unroll
            for (int ii = 0; ii < 4; ii++)
                wmma::load_matrix_sync(af[ii], As + (wr * 64 + ii * 16) * 40 + ks, 40);
            #pragma unroll
            for (int jj = 0; jj < 4; jj++)
                wmma::load_matrix_sync(bfr[jj], Bs + ks * 136 + wc * 64 + jj * 16, 136);
            #pragma unroll
            for (int ii = 0; ii < 4; ii++)
                #pragma unroll
                for (int jj = 0; jj < 4; jj++)
                    wmma::mma_sync(acc[ii][jj], af[ii], bfr[jj], acc[ii][jj]);
        }
        __syncthreads();
        if (i + 3 < nch) load_stage(slot, (i + 3) * 32);
    }

    // bf16 epilogue: per-warp smem staging, ldm=20 (80B pitch, 16B-aligned)
    __syncthreads();
    float* stage = reinterpret_cast<float*>(gsm) + warp * 16 * 20;
    #pragma unroll
    for (int ii = 0; ii < 4; ii++)
        #pragma unroll
        for (int jj = 0; jj < 4; jj++) {
            wmma::store_matrix_sync(stage, acc[ii][jj], 20, wmma::mem_row_major);
            __syncwarp();
            int r = lane >> 1, cbase = (lane & 1) * 8;
            const float* sp = stage + r * 20 + cbase;
            uint4 out;
            out.x = pack_bf2(sp[0], sp[1]);
            out.y = pack_bf2(sp[2], sp[3]);
            out.z = pack_bf2(sp[4], sp[5]);
            out.w = pack_bf2(sp[6], sp[7]);
            bf16* Cp = C + (size_t)(m0 + wr * 64 + ii * 16 + r) * NC
                         + n0 + wc * 64 + jj * 16 + cbase;
            *reinterpret_cast<uint4*>(Cp) = out;
            __syncwarp();
        }
}

// ---------------- router2: warp-per-row (unchanged) ---------------------------
__global__ void __launch_bounds__(256) k_router2(
        const float* __restrict__ ep,
        const int* __restrict__ sid, const int* __restrict__ hc,
        const int* __restrict__ ps,
        const float* __restrict__ rb1, const float* __restrict__ rlg,
        const float* __restrict__ rlb,
        const float* __restrict__ b2, const float* __restrict__ proto,
        float* __restrict__ outC, float* __restrict__ outW) {
    const int warp = threadIdx.x >> 5, lane = threadIdx.x & 31;
    const int row = blockIdx.x * 8 + warp;
    int sI = min(max(sid[row], 0), 2048);
    int hI = min(max(hc[row], 0), 9);
    int pI = min(max(ps[row], 0), 7);
    const float4* h4p  = reinterpret_cast<const float4*>(&g_H1[(size_t)row * HDIM]);
    const float4* b4p  = reinterpret_cast<const float4*>(rb1);
    const float4* ts4p = reinterpret_cast<const float4*>(&g_TS[(size_t)sI * HDIM]);
    const float4* th4p = reinterpret_cast<const float4*>(&g_TH[(size_t)hI * HDIM]);
    const float4* tp4p = reinterpret_cast<const float4*>(&g_TP[(size_t)pI * HDIM]);
    float4 pre[4];
    float s1 = 0.0f, s2 = 0.0f;
    #pragma unroll
    for (int q = 0; q < 4; q++) {
        int c4 = lane + 32 * q;
        float4 h = h4p[c4], b = b4p[c4], ts = ts4p[c4], th = th4p[c4], tp = tp4p[c4];
        pre[q].x = h.x + b.x + ts.x + th.x + tp.x;
        pre[q].y = h.y + b.y + ts.y + th.y + tp.y;
        pre[q].z = h.z + b.z + ts.z + th.z + tp.z;
        pre[q].w = h.w + b.w + ts.w + th.w + tp.w;
        s1 += pre[q].x + pre[q].y + pre[q].z + pre[q].w;
        s2 += pre[q].x * pre[q].x + pre[q].y * pre[q].y
            + pre[q].z * pre[q].z + pre[q].w * pre[q].w;
    }
    s1 = warp_sum(s1);
    s2 = warp_sum(s2);
    float mean = s1 * (1.0f / 512.0f);
    float var  = s2 * (1.0f / 512.0f) - mean * mean;
    float rs = rsqrtf(var + 1e-5f);
    const float4* g4p  = reinterpret_cast<const float4*>(rlg);
    const float4* be4p = reinterpret_cast<const float4*>(rlb);
    float4 hv[4];
    #pragma unroll
    for (int q = 0; q < 4; q++) {
        int c4 = lane + 32 * q;
        float4 g = g4p[c4], be = be4p[c4];
        hv[q].x = gelu_exact((pre[q].x - mean) * rs * g.x + be.x);
        hv[q].y = gelu_exact((pre[q].y - mean) * rs * g.y + be.y);
        hv[q].z = gelu_exact((pre[q].z - mean) * rs * g.z + be.z);
        hv[q].w = gelu_exact((pre[q].w - mean) * rs * g.w + be.w);
    }
    float lg[PROTO];
    #pragma unroll
    for (int l = 0; l < PROTO; l++) {
        const float4* wl = reinterpret_cast<const float4*>(&g_W2T[l * HDIM]);
        float sa = 0.0f;
        #pragma unroll
        for (int q = 0; q < 4; q++) {
            float4 w = wl[lane + 32 * q];
            sa = fmaf(hv[q].x, w.x, sa);
            sa = fmaf(hv[q].y, w.y, sa);
            sa = fmaf(hv[q].z, w.z, sa);
            sa = fmaf(hv[q].w, w.w, sa);
        }
        lg[l] = warp_sum(sa);
    }
    float sw[PROTO];
    if (lane == 0) {
        float w[PROTO];
        #pragma unroll
        for (int i = 0; i < PROTO; i++) w[i] = lg[i] + b2[i];
        float v[PROTO];
        #pragma unroll
        for (int i = 0; i < PROTO; i++) v[i] = w[i];
        float top5[5];
        #pragma unroll
        for (int k = 0; k < 5; k++) {
            int bi = 0; float bv = -1e30f;
            #pragma unroll
            for (int i = 0; i < PROTO; i++)
                if (v[i] > bv) { bv = v[i]; bi = i; }
            top5[k] = bv; v[bi] = -1e30f;
        }
        if (top5[3] - top5[4] < 2e-3f) {
            int pos = atomicAdd(&g_count, 1);
            g_LIST[pos] = row;
        }
        float mx = top5[0];
        float ssum = 0.0f;
        #pragma unroll
        for (int i = 0; i < PROTO; i++) { w[i] = expf(w[i] - mx); ssum += w[i]; }
        float inv = 1.0f / ssum;
        #pragma unroll
        for (int i = 0; i < PROTO; i++) w[i] *= inv;
        bool sel[PROTO];
        #pragma unroll
        for (int i = 0; i < PROTO; i++) sel[i] = false;
        for (int k = 0; k < 4; k++) {
            int bi = -1; float bv = -1e30f;
            #pragma unroll
            for (int i = 0; i < PROTO; i++)
                if (!sel[i] && w[i] > bv) { bv = w[i]; bi = i; }
            sel[bi] = true;
        }
        float s22 = 0.0f;
        #pragma unroll
        for (int i = 0; i < PROTO; i++) { float vv = sel[i] ? w[i] : 0.0f; sw[i] = vv; s22 += vv; }
        float d = 1.0f / fmaxf(s22, 1e-6f);
        #pragma unroll
        for (int i = 0; i < PROTO; i++) sw[i] *= d;
    }
    #pragma unroll
    for (int i = 0; i < PROTO; i++) sw[i] = __shfl_sync(0xffffffffu, sw[i], 0);
    if (lane == 0) {
        float* ow = &outW[(size_t)row * PROTO];
        #pragma unroll
        for (int i = 0; i < PROTO; i++) ow[i] = sw[i];
    }
    const float4* e4p = reinterpret_cast<const float4*>(&ep[(size_t)row * HDIM]);
    float4* oc4p = reinterpret_cast<float4*>(&outC[(size_t)row * HDIM]);
    bf16* frow = &g_FEATSH[(size_t)row * KFN];
    #pragma unroll
    for (int q = 0; q < 4; q++) {
        int c4 = lane + 32 * q;
        float4 c = make_float4(0.f, 0.f, 0.f, 0.f);
        #pragma unroll
        for (int p = 0; p < PROTO; p++) {
            float wv = sw[p];
            float4 pv = reinterpret_cast<const float4*>(&proto[p * HDIM])[c4];
            c.x = fmaf(wv, pv.x, c.x);
            c.y = fmaf(wv, pv.y, c.y);
            c.z = fmaf(wv, pv.z, c.z);
            c.w = fmaf(wv, pv.w, c.w);
        }
        float4 e = e4p[c4];
        oc4p[c4] = c;
        st_bf4(frow + 4 * c4, e);
        st_bf4(frow + 512 + 4 * c4, make_float4(fabsf(e.x - c.x), fabsf(e.y - c.y),
                                                fabsf(e.z - c.z), fabsf(e.w - c.w)));
        st_bf4(frow + 1024 + 4 * c4, make_float4(e.x * c.x, e.y * c.y,
                                                 e.z * c.z, e.w * c.w));
    }
    if (lane < 16) {
        float a = (lane * 2 < PROTO)     ? sw[lane * 2]     : 0.0f;
        float b = (lane * 2 + 1 < PROTO) ? sw[lane * 2 + 1] : 0.0f;
        reinterpret_cast<unsigned*>(frow + 1536)[lane] = pack_bf2(a, b);
    }
}

// ---------------- rescue (exact fp32 path, unchanged) -------------------------
__global__ void __launch_bounds__(128) k_rescue(
        const float* __restrict__ pair, const float* __restrict__ ep,
        const int* __restrict__ sid, const int* __restrict__ hc, const int* __restrict__ ps,
        const float* __restrict__ se, const float* __restrict__ he, const float* __restrict__ soe,
        const float* __restrict__ rw1, const float* __restrict__ rb1,
        const float* __restrict__ rlg, const float* __restrict__ rlb,
        const float* __restrict__ b2, const float* __restrict__ proto,
        float* __restrict__ outC, float* __restrict__ outW) {
    __shared__ float sa[KR];
    __shared__ float shd[HDIM];
    __shared__ double dbuf[4];
    __shared__ float sl[PROTO];
    __shared__ float sw[PROTO];
    int t = threadIdx.x, warp = t >> 5, lane = t & 31;
    int cnt = g_count;
    for (int li = blockIdx.x; li < cnt; li += gridDim.x) {
        int row = g_LIST[li];
        int s = min(max(sid[row], 0), 2048);
        int h = min(max(hc[row], 0), 9);
        int p = min(max(ps[row], 0), 7);
        const float* pr = &pair[(size_t)row * HDIM];
        const float* er = &ep[(size_t)row * HDIM];
        for (int k = t; k < KR; k += 128) {
            float v;
            if      (k < 512)  v = pr[k];
            else if (k < 1024) v = er[k - 512];
            else if (k < 1152) v = se[s * MD + (k - 1024)];
            else if (k < 1280) v = he[h * MD + (k - 1152)];
            else               v = soe[p * MD + (k - 1280)];
            sa[k] = v;
        }
        __syncthreads();
        float hs[4], hcmp[4];
        #pragma unroll
        for (int j = 0; j < 4; j++) { hs[j] = 0.0f; hcmp[j] = 0.0f; }
        for (int k = 0; k < KR; k++) {
            float a = sa[k];
            const float* wr = &rw1[(size_t)k * HDIM];
            #pragma unroll
            for (int j = 0; j < 4; j++) {
                int c = t + j * 128;
                float w = wr[c];
                float pp = a * w;
                float pe = fmaf(a, w, -pp);
                twosum_acc(hs[j], hcmp[j], pp);
                hcmp[j] += pe;
            }
        }
        float pre[4];
        double msum = 0.0;
        #pragma unroll
        for (int j = 0; j < 4; j++) {
            pre[j] = (hs[j] + hcmp[j]) + rb1[t + j * 128];
            msum += (double)pre[j];
        }
        double mean = block_sum_128d(msum, dbuf) * (1.0 / 512.0);
        double vsum = 0.0;
        #pragma unroll
        for (int j = 0; j < 4; j++) {
            double e0 = (double)pre[j] - mean;
            vsum += e0 * e0;
        }
        double var = block_sum_128d(vsum, dbuf) * (1.0 / 512.0);
        float rs = (float)(1.0 / sqrt(var + 1e-5));
        #pragma unroll
        for (int j = 0; j < 4; j++) {
            int c = t + j * 128;
            shd[c] = gelu_exact((float)((double)pre[j] - mean) * rs * rlg[c] + rlb[c]);
        }
        __syncthreads();
        for (int l = warp; l < PROTO; l += 4) {
            float ss = 0.0f, cmp = 0.0f;
            const float* wl = &g_W2T[l * HDIM];
            for (int c = lane; c < HDIM; c += 32) {
                float a = shd[c], w = wl[c];
                float pp = a * w;
                float pe = fmaf(a, w, -pp);
                twosum_acc(ss, cmp, pp);
                cmp += pe;
            }
            #pragma unroll
            for (int o = 16; o; o >>= 1) {
                ss  += __shfl_xor_sync(0xffffffffu, ss, o);
                cmp += __shfl_xor_sync(0xffffffffu, cmp, o);
            }
            if (lane == 0) sl[l] = (ss + cmp) + b2[l];
        }
        __syncthreads();
        if (t == 0) {
            float w[PROTO];
            float mx = -1e30f;
            #pragma unroll
            for (int i = 0; i < PROTO; i++) mx = fmaxf(mx, sl[i]);
            float ssum = 0.0f;
            #pragma unroll
            for (int i = 0; i < PROTO; i++) { w[i] = expf(sl[i] - mx); ssum += w[i]; }
            float inv = 1.0f / ssum;
            #pragma unroll
            for (int i = 0; i < PROTO; i++) w[i] *= inv;
            bool sel[PROTO];
            #pragma unroll
            for (int i = 0; i < PROTO; i++) sel[i] = false;
            for (int k = 0; k < 4; k++) {
                int bi = -1; float bv = -1e30f;
                #pragma unroll
                for (int i = 0; i < PROTO; i++)
                    if (!sel[i] && w[i] > bv) { bv = w[i]; bi = i; }
                sel[bi] = true;
            }
            float s2 = 0.0f;
            #pragma unroll
            for (int i = 0; i < PROTO; i++) { float vv = sel[i] ? w[i] : 0.0f; sw[i] = vv; s2 += vv; }
            float d = 1.0f / fmaxf(s2, 1e-6f);
            #pragma unroll
            for (int i = 0; i < PROTO; i++) sw[i] *= d;
        }
        __syncthreads();
        if (t < PROTO) outW[(size_t)row * PROTO + t] = sw[t];
        bf16* frow = &g_FEATSH[(size_t)row * KFN];
        for (int j = t; j < HDIM; j += 128) {
            float c = 0.0f;
            #pragma unroll
            for (int pp = 0; pp < PROTO; pp++) c += sw[pp] * proto[pp * HDIM + j];
            float e = er[j];
            outC[(size_t)row * HDIM + j] = c;
            frow[j]        = __float2bfloat16_rn(e);
            frow[512 + j]  = __float2bfloat16_rn(fabsf(e - c));
            frow[1024 + j] = __float2bfloat16_rn(e * c);
        }
        if (t < 32) frow[1536 + t] = __float2bfloat16_rn(t < PROTO ? sw[t] : 0.0f);
        __syncthreads();
    }
}

// ---------------- activations: warp-per-row, bf16 in --------------------------
__global__ void __launch_bounds__(256) k_act(
        const float* __restrict__ b_mu, const float* __restrict__ g_mu,
        const float* __restrict__ be_mu, const float* __restrict__ b_mg) {
    const int warp = threadIdx.x >> 5, lane = threadIdx.x & 31;
    const int row = blockIdx.x * 8 + warp;
    const bf16* h12 = &g_H12H[(size_t)row * 1024];
    const float4* bm4 = reinterpret_cast<const float4*>(b_mu);
    float4 m[4];
    float s1 = 0.0f, s2 = 0.0f;
    #pragma unroll
    for (int q = 0; q < 4; q++) {
        int c4 = lane + 32 * q;
        float4 h = ld_bf4(h12 + 4 * c4);
        float4 b = bm4[c4];
        m[q].x = h.x + b.x; m[q].y = h.y + b.y;
        m[q].z = h.z + b.z; m[q].w = h.w + b.w;
        s1 += m[q].x + m[q].y + m[q].z + m[q].w;
        s2 += m[q].x * m[q].x + m[q].y * m[q].y + m[q].z * m[q].z + m[q].w * m[q].w;
    }
    s1 = warp_sum(s1);
    s2 = warp_sum(s2);
    float mean = s1 * (1.0f / 512.0f);
    float var  = s2 * (1.0f / 512.0f) - mean * mean;
    float rs = rsqrtf(var + 1e-5f);
    const float4* g4p  = reinterpret_cast<const float4*>(g_mu);
    const float4* be4p = reinterpret_cast<const float4*>(be_mu);
    const float4* bg4p = reinterpret_cast<const float4*>(b_mg);
    bf16* xm = &g_HMUH[(size_t)row * HDIM];
    bf16* xg = &g_HMGH[(size_t)row * HDIM];
    #pragma unroll
    for (int q = 0; q < 4; q++) {
        int c4 = lane + 32 * q;
        float4 g = g4p[c4], be = be4p[c4];
        float4 o;
        o.x = gelu_exact((m[q].x - mean) * rs * g.x + be.x);
        o.y = gelu_exact((m[q].y - mean) * rs * g.y + be.y);
        o.z = gelu_exact((m[q].z - mean) * rs * g.z + be.z);
        o.w = gelu_exact((m[q].w - mean) * rs * g.w + be.w);
        st_bf4(xm + 4 * c4, o);
        float4 gg = ld_bf4(h12 + 512 + 4 * c4);
        float4 bg = bg4p[c4];
        float4 og;
        og.x = gelu_exact(gg.x + bg.x);
        og.y = gelu_exact(gg.y + bg.y);
        og.z = gelu_exact(gg.z + bg.z);
        og.w = gelu_exact(gg.w + bg.w);
        st_bf4(xg + 4 * c4, og);
    }
}

// ---------------- final: warp-per-row, bf16 in --------------------------------
__global__ void __launch_bounds__(256) k_final(
        const float* __restrict__ ep, const float* __restrict__ mub2,
        const float* __restrict__ mgb2, const float* __restrict__ ng,
        const float* __restrict__ nb, float* __restrict__ outU) {
    const int warp = threadIdx.x >> 5, lane = threadIdx.x & 31;
    const int row = blockIdx.x * 8 + warp;
    const float4* e4p  = reinterpret_cast<const float4*>(&ep[(size_t)row * HDIM]);
    const bf16* dp  = &g_DELTAH[(size_t)row * HDIM];
    const bf16* gpp = &g_GATEH[(size_t)row * HDIM];
    const float4* db4p = reinterpret_cast<const float4*>(mub2);
    const float4* gb4p = reinterpret_cast<const float4*>(mgb2);
    float4 u[4];
    float s1 = 0.0f, s2 = 0.0f;
    #pragma unroll
    for (int q = 0; q < 4; q++) {
        int c4 = lane + 32 * q;
        float4 e = e4p[c4];
        float4 d = ld_bf4(dp + 4 * c4);
        float4 gp = ld_bf4(gpp + 4 * c4);
        float4 db = db4p[c4], gb = gb4p[c4];
        u[q].x = e.x + RSCALE * (1.0f / (1.0f + expf(-(gp.x + gb.x)))) * (d.x + db.x);
        u[q].y = e.y + RSCALE * (1.0f / (1.0f + expf(-(gp.y + gb.y)))) * (d.y + db.y);
        u[q].z = e.z + RSCALE * (1.0f / (1.0f + expf(-(gp.z + gb.z)))) * (d.z + db.z);
        u[q].w = e.w + RSCALE * (1.0f / (1.0f + expf(-(gp.w + gb.w)))) * (d.w + db.w);
        s1 += u[q].x + u[q].y + u[q].z + u[q].w;
        s2 += u[q].x * u[q].x + u[q].y * u[q].y + u[q].z * u[q].z + u[q].w * u[q].w;
    }
    s1 = warp_sum(s1);
    s2 = warp_sum(s2);
    float mean = s1 * (1.0f / 512.0f);
    float var  = s2 * (1.0f / 512.0f) - mean * mean;
    float rs = rsqrtf(var + 1e-5f);
    const float4* g4p = reinterpret_cast<const float4*>(ng);
    const float4* b4p = reinterpret_cast<const float4*>(nb);
    float4* ou = reinterpret_cast<float4*>(&outU[(size_t)row * HDIM]);
    #pragma unroll
    for (int q = 0; q < 4; q++) {
        int c4 = lane + 32 * q;
        float4 g = g4p[c4], b = b4p[c4];
        float4 o;
        o.x = (u[q].x - mean) * rs * g.x + b.x;
        o.y = (u[q].y - mean) * rs * g.y + b.y;
        o.z = (u[q].z - mean) * rs * g.z + b.z;
        o.w = (u[q].w - mean) * rs * g.w + b.w;
        ou[c4] = o;
    }
}

// ---------------- launch ----------------
extern "C" void kernel_launch(void* const* d_in, const int* in_sizes, int n_in,
                              void* d_out, int out_size) {
    const float* pair = (const float*)d_in[0];
    const float* ep   = (const float*)d_in[1];
    const int*   sid  = (const int*)d_in[2];
    const int*   hc   = (const int*)d_in[3];
    const int*   ps   = (const int*)d_in[4];
    const float* se   = (const float*)d_in[5];
    const float* he   = (const float*)d_in[6];
    const float* soe  = (const float*)d_in[7];
    const float* proto= (const float*)d_in[8];
    const float* rw1  = (const float*)d_in[9];
    const float* rb1  = (const float*)d_in[10];
    const float* rlg  = (const float*)d_in[11];
    const float* rlb  = (const float*)d_in[12];
    const float* rw2  = (const float*)d_in[13];
    const float* rb2  = (const float*)d_in[14];
    const float* muw1 = (const float*)d_in[15];
    const float* mub1 = (const float*)d_in[16];
    const float* mulg = (const float*)d_in[17];
    const float* mulb = (const float*)d_in[18];
    const float* muw2 = (const float*)d_in[19];
    const float* mub2 = (const float*)d_in[20];
    const float* mgw1 = (const float*)d_in[21];
    const float* mgb1 = (const float*)d_in[22];
    const float* mgw2 = (const float*)d_in[23];
    const float* mgb2 = (const float*)d_in[24];
    const float* ng   = (const float*)d_in[25];
    const float* nb   = (const float*)d_in[26];

    float* outU = (float*)d_out;
    float* outC = outU + (size_t)NROWS * HDIM;
    float* outW = outC + (size_t)NROWS * HDIM;

    float *pH1;
    bf16 *pFEATSH, *pH12H, *pHMUH, *pHMGH, *pDELTAH, *pGATEH, *pW1, *pW2MU, *pW2MG;
    cudaGetSymbolAddress((void**)&pH1,     g_H1);
    cudaGetSymbolAddress((void**)&pH12H,   g_H12H);
    cudaGetSymbolAddress((void**)&pDELTAH, g_DELTAH);
    cudaGetSymbolAddress((void**)&pGATEH,  g_GATEH);
    cudaGetSymbolAddress((void**)&pFEATSH, g_FEATSH);
    cudaGetSymbolAddress((void**)&pHMUH,   g_HMUH);
    cudaGetSymbolAddress((void**)&pHMGH,   g_HMGH);
    cudaGetSymbolAddress((void**)&pW1,     g_W1);
    cudaGetSymbolAddress((void**)&pW2MU,   g_W2MU);
    cudaGetSymbolAddress((void**)&pW2MG,   g_W2MG);

    static bool attr_set = false;
    if (!attr_set) {
        cudaFuncSetAttribute(gemm_router2, cudaFuncAttributeMaxDynamicSharedMemorySize,
                             3 * GR_STG);
        cudaFuncSetAttribute(gemm_bf16o, cudaFuncAttributeMaxDynamicSharedMemorySize,
                             3 * GB_STG);
        attr_set = true;
    }

    k_prep<<<4096, 256>>>(rw1, rw2, muw1, mgw1, muw2, mgw2, se, he, soe, proto);
    k_gather<<<NROWS, 128>>>(pair, ep);
    {
        dim3 grid(HDIM / 64, NROWS / 256);     // (8, 256)
        gemm_router2<<<grid, 256, 3 * GR_STG>>>(pH1);
    }
    k_router2<<<NROWS / 8, 256>>>(ep, sid, hc, ps, rb1, rlg, rlb, rb2, proto, outC, outW);
    k_rescue<<<2048, 128>>>(pair, ep, sid, hc, ps, se, he, soe,
                            rw1, rb1, rlg, rlb, rb2, proto, outC, outW);
    {
        dim3 grid(1024 / 128, NROWS / 256);    // (8, 256)
        gemm_bf16o<<<grid, 256, 3 * GB_STG>>>(pFEATSH, pW1, pH12H, KFN, 1024);
    }
    k_act<<<NROWS / 8, 256>>>(mub1, mulg, mulb, mgb1);
    {
        dim3 grid(HDIM / 128, NROWS / 256);    // (4, 256)
        gemm_bf16o<<<grid, 256, 3 * GB_STG>>>(pHMUH, pW2MU, pDELTAH, HDIM, HDIM);
        gemm_bf16o<<<grid, 256, 3 * GB_STG>>>(pHMGH, pW2MG, pGATEH, HDIM, HDIM);
    }
    k_final<<<NROWS / 8, 256>>>(ep, mub2, mgb2, ng, nb, outU);
}